// round 1
// baseline (speedup 1.0000x reference)
#include <cuda_runtime.h>

#define NH 16
#define NB 4
#define SQ 1024
#define DM 1024
#define DK 64
#define MR (NB * SQ)   /* 4096 rows of (b,s) */
#define HB (NH * NB)   /* 64 (h,b) pairs     */

// Scratch (allocation-free rule: __device__ globals)
__device__ float g_q[(size_t)HB * SQ * DK];
__device__ float g_k[(size_t)HB * SQ * DK];
__device__ float g_v[(size_t)HB * SQ * DK];
__device__ float g_concat[(size_t)MR * DM];
__device__ float g_rmax[HB * SQ];
__device__ float g_rsuminv[HB * SQ];

// ---------------------------------------------------------------------------
// Kernel 1: per-head projections  O[h] = X @ W[h]
//   X: [4096, 1024] row-major, W[h]: [1024, 64] row-major
//   BM=128, BN=64, BK=16, 256 threads, 8x4 micro-tile.
// ---------------------------------------------------------------------------
__global__ __launch_bounds__(256) void proj_kernel(
    const float* __restrict__ Xq, const float* __restrict__ Xk, const float* __restrict__ Xv,
    const float* __restrict__ Wq, const float* __restrict__ Wk, const float* __restrict__ Wv)
{
    const int which = blockIdx.z;
    const float* X = (which == 0) ? Xq : (which == 1) ? Xk : Xv;
    const float* W = (which == 0) ? Wq : (which == 1) ? Wk : Wv;
    float* O       = (which == 0) ? g_q : (which == 1) ? g_k : g_v;
    const int h    = blockIdx.y;
    const int row0 = blockIdx.x * 128;

    __shared__ float As[16][132];   // [k][row], pad keeps store conflicts at 2-way
    __shared__ float Bs[16][64];    // [k][col]

    const int t  = threadIdx.x;
    const int tx = t & 15, ty = t >> 4;
    const float* Wh = W + (size_t)h * DM * DK;

    float acc[8][4];
#pragma unroll
    for (int i = 0; i < 8; i++)
#pragma unroll
        for (int j = 0; j < 4; j++) acc[i][j] = 0.f;

    for (int kt = 0; kt < DM; kt += 16) {
        // A tile 128x16 (transposed store)
#pragma unroll
        for (int u = 0; u < 2; u++) {
            int idx = t + u * 256;
            int row = idx >> 2, c4 = idx & 3;
            float4 a = *(const float4*)(X + (size_t)(row0 + row) * DM + kt + c4 * 4);
            As[c4 * 4 + 0][row] = a.x;
            As[c4 * 4 + 1][row] = a.y;
            As[c4 * 4 + 2][row] = a.z;
            As[c4 * 4 + 3][row] = a.w;
        }
        // B tile 16x64 (direct)
        {
            int r = t >> 4, c4 = t & 15;
            *(float4*)&Bs[r][c4 * 4] = *(const float4*)(Wh + (size_t)(kt + r) * DK + c4 * 4);
        }
        __syncthreads();
#pragma unroll
        for (int kk = 0; kk < 16; kk++) {
            float4 a0 = *(float4*)&As[kk][ty * 8];
            float4 a1 = *(float4*)&As[kk][ty * 8 + 4];
            float4 b4 = *(float4*)&Bs[kk][tx * 4];
            float av[8] = {a0.x, a0.y, a0.z, a0.w, a1.x, a1.y, a1.z, a1.w};
            float bv[4] = {b4.x, b4.y, b4.z, b4.w};
#pragma unroll
            for (int i = 0; i < 8; i++)
#pragma unroll
                for (int j = 0; j < 4; j++) acc[i][j] += av[i] * bv[j];
        }
        __syncthreads();
    }
#pragma unroll
    for (int i = 0; i < 8; i++) {
        int r = row0 + ty * 8 + i;
        float4 o = make_float4(acc[i][0], acc[i][1], acc[i][2], acc[i][3]);
        *(float4*)(O + ((size_t)h * MR + r) * DK + tx * 4) = o;
    }
}

// ---------------------------------------------------------------------------
// Kernel 2: scores = (Q Kt) * 1/8, masked, written straight into d_out's
// `masked` region [H,B,S,S]. Per (h,b): 1024x1024x64 GEMM. 64x64 tile.
// ---------------------------------------------------------------------------
__global__ __launch_bounds__(256) void scores_kernel(
    const int* __restrict__ mask, float* __restrict__ sc)
{
    const int hb = blockIdx.z;      // h*NB + b
    const int b  = hb & 3;
    const int q0 = blockIdx.x * 64;
    const int m0 = blockIdx.y * 64;

    __shared__ float Qt[64][65];    // [k][qrow]
    __shared__ float Kt[64][65];    // [k][mcol]

    const int t  = threadIdx.x;
    const int tx = t & 15, ty = t >> 4;
    const float* qb = g_q + (size_t)hb * SQ * DK;
    const float* kb = g_k + (size_t)hb * SQ * DK;

#pragma unroll
    for (int u = 0; u < 4; u++) {
        int idx = t + u * 256;
        int row = idx >> 4, c4 = idx & 15;
        float4 a = *(const float4*)(qb + (size_t)(q0 + row) * DK + c4 * 4);
        Qt[c4 * 4 + 0][row] = a.x; Qt[c4 * 4 + 1][row] = a.y;
        Qt[c4 * 4 + 2][row] = a.z; Qt[c4 * 4 + 3][row] = a.w;
        float4 c = *(const float4*)(kb + (size_t)(m0 + row) * DK + c4 * 4);
        Kt[c4 * 4 + 0][row] = c.x; Kt[c4 * 4 + 1][row] = c.y;
        Kt[c4 * 4 + 2][row] = c.z; Kt[c4 * 4 + 3][row] = c.w;
    }
    __syncthreads();

    float acc[4][4];
#pragma unroll
    for (int i = 0; i < 4; i++)
#pragma unroll
        for (int j = 0; j < 4; j++) acc[i][j] = 0.f;

#pragma unroll 16
    for (int kk = 0; kk < 64; kk++) {
        float a[4], bv[4];
#pragma unroll
        for (int i = 0; i < 4; i++) a[i] = Qt[kk][ty * 4 + i];
#pragma unroll
        for (int j = 0; j < 4; j++) bv[j] = Kt[kk][tx * 4 + j];
#pragma unroll
        for (int i = 0; i < 4; i++)
#pragma unroll
            for (int j = 0; j < 4; j++) acc[i][j] += a[i] * bv[j];
    }

    const float scale  = 0.125f;                       // 1/sqrt(64)
    const float NEGINF = __int_as_float(0xff800000u);
#pragma unroll
    for (int i = 0; i < 4; i++) {
        int qi = q0 + ty * 4 + i;
        int4 mk = *(const int4*)(mask + ((size_t)b * SQ + qi) * SQ + m0 + tx * 4);
        float4 o;
        o.x = mk.x ? acc[i][0] * scale : NEGINF;
        o.y = mk.y ? acc[i][1] * scale : NEGINF;
        o.z = mk.z ? acc[i][2] * scale : NEGINF;
        o.w = mk.w ? acc[i][3] * scale : NEGINF;
        *(float4*)(sc + ((size_t)hb * SQ + qi) * SQ + m0 + tx * 4) = o;
    }
}

// ---------------------------------------------------------------------------
// Kernel 3: per-row softmax stats (max, 1/sumexp). One warp per row of 1024.
// ---------------------------------------------------------------------------
__global__ __launch_bounds__(256) void stats_kernel(const float* __restrict__ sc)
{
    const int gw   = (blockIdx.x * 256 + threadIdx.x) >> 5;   // row id, 0..65535
    const int lane = threadIdx.x & 31;
    const float* row = sc + (size_t)gw * SQ;

    float v[32];
    float m = __int_as_float(0xff800000u);
#pragma unroll
    for (int i = 0; i < 8; i++) {
        float4 x = *(const float4*)(row + lane * 4 + i * 128);
        v[i * 4 + 0] = x.x; v[i * 4 + 1] = x.y; v[i * 4 + 2] = x.z; v[i * 4 + 3] = x.w;
        m = fmaxf(m, fmaxf(fmaxf(x.x, x.y), fmaxf(x.z, x.w)));
    }
#pragma unroll
    for (int o = 16; o > 0; o >>= 1) m = fmaxf(m, __shfl_xor_sync(0xffffffffu, m, o));
    float s = 0.f;
#pragma unroll
    for (int i = 0; i < 32; i++) s += __expf(v[i] - m);
#pragma unroll
    for (int o = 16; o > 0; o >>= 1) s += __shfl_xor_sync(0xffffffffu, s, o);
    if (lane == 0) { g_rmax[gw] = m; g_rsuminv[gw] = 1.0f / s; }
}

// ---------------------------------------------------------------------------
// Kernel 4: attn_out = softmax(S) @ V, exp applied on-the-fly while staging P.
// Per (h,b): 1024x64x1024 GEMM. BM=64, BN=64, BK=16. Writes concat layout.
// ---------------------------------------------------------------------------
__global__ __launch_bounds__(256) void av_kernel(const float* __restrict__ sc)
{
    const int hb = blockIdx.y;
    const int h  = hb >> 2, b = hb & 3;
    const int q0 = blockIdx.x * 64;

    __shared__ float Ps[16][65];    // [m'][qrow], exp-normalized
    __shared__ float Vs[16][64];    // [m'][col]

    const int t  = threadIdx.x;
    const int tx = t & 15, ty = t >> 4;
    const float* srow = sc + ((size_t)hb * SQ + q0) * SQ;
    const float* vb   = g_v + (size_t)hb * SQ * DK;

    const int prow = t >> 2, pc4 = t & 3;    // P loader: 64 rows x 4 float4
    const float rmax = g_rmax[hb * SQ + q0 + prow];
    const float rsi  = g_rsuminv[hb * SQ + q0 + prow];
    const int vr = t >> 4, vc4 = t & 15;     // V loader: 16 rows x 16 float4

    float acc[4][4];
#pragma unroll
    for (int i = 0; i < 4; i++)
#pragma unroll
        for (int j = 0; j < 4; j++) acc[i][j] = 0.f;

    for (int mt = 0; mt < SQ; mt += 16) {
        float4 p = *(const float4*)(srow + (size_t)prow * SQ + mt + pc4 * 4);
        Ps[pc4 * 4 + 0][prow] = __expf(p.x - rmax) * rsi;
        Ps[pc4 * 4 + 1][prow] = __expf(p.y - rmax) * rsi;
        Ps[pc4 * 4 + 2][prow] = __expf(p.z - rmax) * rsi;
        Ps[pc4 * 4 + 3][prow] = __expf(p.w - rmax) * rsi;
        *(float4*)&Vs[vr][vc4 * 4] = *(const float4*)(vb + (size_t)(mt + vr) * DK + vc4 * 4);
        __syncthreads();
#pragma unroll
        for (int kk = 0; kk < 16; kk++) {
            float a[4];
#pragma unroll
            for (int i = 0; i < 4; i++) a[i] = Ps[kk][ty * 4 + i];
            float4 b4 = *(float4*)&Vs[kk][tx * 4];
            float bv[4] = {b4.x, b4.y, b4.z, b4.w};
#pragma unroll
            for (int i = 0; i < 4; i++)
#pragma unroll
                for (int j = 0; j < 4; j++) acc[i][j] += a[i] * bv[j];
        }
        __syncthreads();
    }
#pragma unroll
    for (int i = 0; i < 4; i++) {
        int qi = q0 + ty * 4 + i;
        float4 o = make_float4(acc[i][0], acc[i][1], acc[i][2], acc[i][3]);
        *(float4*)(g_concat + ((size_t)b * SQ + qi) * DM + h * DK + tx * 4) = o;
    }
}

// ---------------------------------------------------------------------------
// Kernel 5: out = concat @ Wo   [4096,1024] x [1024,1024]
//   BM=128, BN=64, BK=16, 256 threads, 8x4 micro-tile.
// ---------------------------------------------------------------------------
__global__ __launch_bounds__(256) void outproj_kernel(
    const float* __restrict__ Wo, float* __restrict__ out)
{
    const int row0 = blockIdx.x * 128;
    const int n0   = blockIdx.y * 64;

    __shared__ float As[16][132];
    __shared__ float Bs[16][64];

    const int t  = threadIdx.x;
    const int tx = t & 15, ty = t >> 4;

    float acc[8][4];
#pragma unroll
    for (int i = 0; i < 8; i++)
#pragma unroll
        for (int j = 0; j < 4; j++) acc[i][j] = 0.f;

    for (int kt = 0; kt < DM; kt += 16) {
#pragma unroll
        for (int u = 0; u < 2; u++) {
            int idx = t + u * 256;
            int row = idx >> 2, c4 = idx & 3;
            float4 a = *(const float4*)(g_concat + (size_t)(row0 + row) * DM + kt + c4 * 4);
            As[c4 * 4 + 0][row] = a.x;
            As[c4 * 4 + 1][row] = a.y;
            As[c4 * 4 + 2][row] = a.z;
            As[c4 * 4 + 3][row] = a.w;
        }
        {
            int r = t >> 4, c4 = t & 15;
            *(float4*)&Bs[r][c4 * 4] = *(const float4*)(Wo + (size_t)(kt + r) * DM + n0 + c4 * 4);
        }
        __syncthreads();
#pragma unroll
        for (int kk = 0; kk < 16; kk++) {
            float4 a0 = *(float4*)&As[kk][ty * 8];
            float4 a1 = *(float4*)&As[kk][ty * 8 + 4];
            float4 b4 = *(float4*)&Bs[kk][tx * 4];
            float av[8] = {a0.x, a0.y, a0.z, a0.w, a1.x, a1.y, a1.z, a1.w};
            float bv[4] = {b4.x, b4.y, b4.z, b4.w};
#pragma unroll
            for (int i = 0; i < 8; i++)
#pragma unroll
                for (int j = 0; j < 4; j++) acc[i][j] += av[i] * bv[j];
        }
        __syncthreads();
    }
#pragma unroll
    for (int i = 0; i < 8; i++) {
        int r = row0 + ty * 8 + i;
        float4 o = make_float4(acc[i][0], acc[i][1], acc[i][2], acc[i][3]);
        *(float4*)(out + (size_t)r * DM + n0 + tx * 4) = o;
    }
}

// ---------------------------------------------------------------------------
extern "C" void kernel_launch(void* const* d_in, const int* in_sizes, int n_in,
                              void* d_out, int out_size)
{
    const float* q    = (const float*)d_in[0];
    const float* k    = (const float*)d_in[1];
    const float* v    = (const float*)d_in[2];
    const int*   mask = (const int*)  d_in[3];
    const float* Wq   = (const float*)d_in[4];
    const float* Wk   = (const float*)d_in[5];
    const float* Wv   = (const float*)d_in[6];
    const float* Wo   = (const float*)d_in[7];

    float* out = (float*)d_out;                 // [B,S,DM] = 4194304 floats
    float* sc  = out + (size_t)MR * DM;         // masked scores [H,B,S,S]

    proj_kernel   <<<dim3(MR / 128, NH, 3), 256>>>(q, k, v, Wq, Wk, Wv);
    scores_kernel <<<dim3(SQ / 64, SQ / 64, HB), 256>>>(mask, sc);
    stats_kernel  <<<dim3(HB * SQ / 8), 256>>>(sc);
    av_kernel     <<<dim3(SQ / 64, HB), 256>>>(sc);
    outproj_kernel<<<dim3(MR / 128, DM / 64), 256>>>(Wo, out);
}

// round 2
// speedup vs baseline: 1.8843x; 1.8843x over previous
#include <cuda_runtime.h>

#define NH 16
#define NB 4
#define SQ 1024
#define DM 1024
#define DK 64
#define MR (NB * SQ)   /* 4096 rows of (b,s) */
#define HB (NH * NB)   /* 64 (h,b) pairs     */

// Scratch (allocation-free rule: __device__ globals)
__device__ float g_q[(size_t)HB * SQ * DK];
__device__ float g_k[(size_t)HB * SQ * DK];
__device__ float g_v[(size_t)HB * SQ * DK];
__device__ float g_concat[(size_t)MR * DM];

__device__ __forceinline__ float f2tf(float x) {
    unsigned u;
    asm("cvt.rna.tf32.f32 %0, %1;" : "=r"(u) : "f"(x));
    return __uint_as_float(u);
}

__device__ __forceinline__ void mma8(float* d, const float* a, const float* b) {
    asm volatile(
        "mma.sync.aligned.m16n8k8.row.col.f32.tf32.tf32.f32 "
        "{%0,%1,%2,%3}, {%4,%5,%6,%7}, {%8,%9}, {%0,%1,%2,%3};\n"
        : "+f"(d[0]), "+f"(d[1]), "+f"(d[2]), "+f"(d[3])
        : "r"(__float_as_uint(a[0])), "r"(__float_as_uint(a[1])),
          "r"(__float_as_uint(a[2])), "r"(__float_as_uint(a[3])),
          "r"(__float_as_uint(b[0])), "r"(__float_as_uint(b[1])));
}

// ---------------------------------------------------------------------------
// Kernel 1: per-head projections via tf32 MMA.
//   C[4096, 1024(h,k)] = X[4096,1024] @ W  (W[h][d][k] gathered per column)
//   BM=128, BN=128, BK=32, 256 threads (8 warps as 4x2, warp tile 32x64).
// ---------------------------------------------------------------------------
__global__ __launch_bounds__(256) void proj_mma(
    const float* __restrict__ Xq, const float* __restrict__ Xk, const float* __restrict__ Xv,
    const float* __restrict__ Wq, const float* __restrict__ Wk, const float* __restrict__ Wv)
{
    const int which = blockIdx.z;
    const float* X = (which == 0) ? Xq : (which == 1) ? Xk : Xv;
    const float* W = (which == 0) ? Wq : (which == 1) ? Wk : Wv;
    float* O       = (which == 0) ? g_q : (which == 1) ? g_k : g_v;
    const int row0 = blockIdx.x * 128;
    const int col0 = blockIdx.y * 128;

    __shared__ float As[32][136];   // [k][m], stride 136 -> conflict-free frag loads
    __shared__ float Bs[32][136];   // [k][n]

    const int t    = threadIdx.x;
    const int warp = t >> 5, lane = t & 31;
    const int gid  = lane >> 2, tig = lane & 3;
    const int mb   = (warp >> 1) * 32;
    const int nb   = (warp & 1) * 64;

    float acc[2][8][4] = {};

    for (int kt = 0; kt < DM; kt += 32) {
#pragma unroll
        for (int u = 0; u < 4; u++) {               // A tile 128x32, transposed store
            int idx = t + u * 256;
            int row = idx & 127, k4 = idx >> 7;
            float4 a = *(const float4*)(X + (size_t)(row0 + row) * DM + kt + k4 * 4);
            As[k4 * 4 + 0][row] = f2tf(a.x);
            As[k4 * 4 + 1][row] = f2tf(a.y);
            As[k4 * 4 + 2][row] = f2tf(a.z);
            As[k4 * 4 + 3][row] = f2tf(a.w);
        }
#pragma unroll
        for (int u = 0; u < 4; u++) {               // B tile 32x128 (per-column head)
            int idx = t + u * 256;
            int k = idx >> 5, c4 = idx & 31;
            int col = col0 + c4 * 4;
            int h = col >> 6, kk = col & 63;
            float4 bv = *(const float4*)(W + (size_t)h * DM * DK + (size_t)(kt + k) * DK + kk);
            *(float4*)&Bs[k][c4 * 4] = make_float4(f2tf(bv.x), f2tf(bv.y), f2tf(bv.z), f2tf(bv.w));
        }
        __syncthreads();
#pragma unroll
        for (int ks = 0; ks < 4; ks++) {
            const int k0 = ks * 8;
            float a[2][4], b[8][2];
#pragma unroll
            for (int mt = 0; mt < 2; mt++) {
                int m = mb + mt * 16 + gid;
                a[mt][0] = As[k0 + tig][m];
                a[mt][1] = As[k0 + tig][m + 8];
                a[mt][2] = As[k0 + tig + 4][m];
                a[mt][3] = As[k0 + tig + 4][m + 8];
            }
#pragma unroll
            for (int nt = 0; nt < 8; nt++) {
                int n = nb + nt * 8 + gid;
                b[nt][0] = Bs[k0 + tig][n];
                b[nt][1] = Bs[k0 + tig + 4][n];
            }
#pragma unroll
            for (int mt = 0; mt < 2; mt++)
#pragma unroll
                for (int nt = 0; nt < 8; nt++) mma8(acc[mt][nt], a[mt], b[nt]);
        }
        __syncthreads();
    }
#pragma unroll
    for (int mt = 0; mt < 2; mt++) {
        int r0 = row0 + mb + mt * 16 + gid;
        int bb = r0 >> 10, s0 = r0 & 1023;
#pragma unroll
        for (int nt = 0; nt < 8; nt++) {
            int col = col0 + nb + nt * 8 + 2 * tig;
            int h = col >> 6, kk = col & 63;
            float* base = O + (size_t)(h * NB + bb) * SQ * DK;
            *(float2*)(base + (size_t)s0 * DK + kk)       = make_float2(acc[mt][nt][0], acc[mt][nt][1]);
            *(float2*)(base + (size_t)(s0 + 8) * DK + kk) = make_float2(acc[mt][nt][2], acc[mt][nt][3]);
        }
    }
}

// ---------------------------------------------------------------------------
// Kernel 2: fused attention. Per CTA: (hb, 128 q-rows). Streams 8 key tiles
// of 128: S = QK^T*0.125 (tf32 MMA) -> mask -> write scores to d_out ->
// exp (no max-sub; exp(-inf)=0) -> row-sum in regs -> P@V tf32 MMA into
// register accumulators -> normalize -> write concat. No stats/av kernels.
// ---------------------------------------------------------------------------
__global__ __launch_bounds__(256) void attn_mma(
    const int* __restrict__ mask, float* __restrict__ sc)
{
    extern __shared__ float sm[];
    float (*Qs)[136] = (float(*)[136])sm;                        // [64][136]
    float (*Ks)[136] = (float(*)[136])(sm + 64 * 136);           // [64][136]
    float (*Vs)[72]  = (float(*)[72]) (sm + 2 * 64 * 136);       // [128][72]
    float (*Ps)[136] = (float(*)[136])(sm + 2 * 64 * 136 + 128 * 72); // [128][136]

    const int hb = blockIdx.y;
    const int h  = hb >> 2, b = hb & 3;
    const int q0 = blockIdx.x * 128;
    const int t = threadIdx.x, warp = t >> 5, lane = t & 31;
    const int gid = lane >> 2, tig = lane & 3;
    const int mb  = warp * 16;
    const int mq0 = mb + gid, mq1 = mb + gid + 8;

    // load Q tile once (transposed, tf32)
    const float* qbase = g_q + ((size_t)hb * SQ + q0) * DK;
#pragma unroll
    for (int u = 0; u < 8; u++) {
        int idx = t + u * 256;
        int row = idx >> 4, c4 = idx & 15;
        float4 a = *(const float4*)(qbase + (size_t)row * DK + c4 * 4);
        Qs[c4 * 4 + 0][row] = f2tf(a.x);
        Qs[c4 * 4 + 1][row] = f2tf(a.y);
        Qs[c4 * 4 + 2][row] = f2tf(a.z);
        Qs[c4 * 4 + 3][row] = f2tf(a.w);
    }

    float Oacc[8][4] = {};
    float rs0 = 0.f, rs1 = 0.f;
    const float NEGINF = __int_as_float(0xff800000u);
    const float* kbase = g_k + (size_t)hb * SQ * DK;
    const float* vbase = g_v + (size_t)hb * SQ * DK;

    for (int kb = 0; kb < 8; kb++) {
        // load K (transposed) + V (direct) tiles
#pragma unroll
        for (int u = 0; u < 8; u++) {
            int idx = t + u * 256;
            int row = idx >> 4, c4 = idx & 15;
            float4 kx = *(const float4*)(kbase + (size_t)(kb * 128 + row) * DK + c4 * 4);
            Ks[c4 * 4 + 0][row] = f2tf(kx.x);
            Ks[c4 * 4 + 1][row] = f2tf(kx.y);
            Ks[c4 * 4 + 2][row] = f2tf(kx.z);
            Ks[c4 * 4 + 3][row] = f2tf(kx.w);
            float4 vx = *(const float4*)(vbase + (size_t)(kb * 128 + row) * DK + c4 * 4);
            *(float4*)&Vs[row][c4 * 4] = make_float4(f2tf(vx.x), f2tf(vx.y), f2tf(vx.z), f2tf(vx.w));
        }
        __syncthreads();

        // S = Q @ K^T  (warp strip: 16 q-rows x 128 keys)
        float Sacc[16][4] = {};
#pragma unroll
        for (int ks = 0; ks < 8; ks++) {
            int k0 = ks * 8;
            float a[4];
            a[0] = Qs[k0 + tig][mq0];
            a[1] = Qs[k0 + tig][mq1];
            a[2] = Qs[k0 + tig + 4][mq0];
            a[3] = Qs[k0 + tig + 4][mq1];
#pragma unroll
            for (int nt = 0; nt < 16; nt++) {
                float bf[2];
                bf[0] = Ks[k0 + tig][nt * 8 + gid];
                bf[1] = Ks[k0 + tig + 4][nt * 8 + gid];
                mma8(Sacc[nt], a, bf);
            }
        }

        // scale, mask, write scores, exp -> Ps + rowsum
        const int r0 = q0 + mq0, r1 = q0 + mq1;
        const int* mrow0 = mask + ((size_t)b * SQ + r0) * SQ + kb * 128;
        const int* mrow1 = mask + ((size_t)b * SQ + r1) * SQ + kb * 128;
        float* srow0 = sc + ((size_t)hb * SQ + r0) * SQ + kb * 128;
        float* srow1 = sc + ((size_t)hb * SQ + r1) * SQ + kb * 128;
#pragma unroll
        for (int nt = 0; nt < 16; nt++) {
            int cl = nt * 8 + 2 * tig;
            int2 m0v = *(const int2*)(mrow0 + cl);
            int2 m1v = *(const int2*)(mrow1 + cl);
            float s00 = m0v.x ? Sacc[nt][0] * 0.125f : NEGINF;
            float s01 = m0v.y ? Sacc[nt][1] * 0.125f : NEGINF;
            float s10 = m1v.x ? Sacc[nt][2] * 0.125f : NEGINF;
            float s11 = m1v.y ? Sacc[nt][3] * 0.125f : NEGINF;
            *(float2*)(srow0 + cl) = make_float2(s00, s01);
            *(float2*)(srow1 + cl) = make_float2(s10, s11);
            float e00 = __expf(s00), e01 = __expf(s01);
            float e10 = __expf(s10), e11 = __expf(s11);
            rs0 += e00 + e01;
            rs1 += e10 + e11;
            Ps[cl][mq0]     = f2tf(e00);
            Ps[cl + 1][mq0] = f2tf(e01);
            Ps[cl][mq1]     = f2tf(e10);
            Ps[cl + 1][mq1] = f2tf(e11);
        }
        __syncthreads();

        // O += P @ V  (warp strip: 16 q-rows x 64 dk, K=128 keys)
#pragma unroll
        for (int ks = 0; ks < 16; ks++) {
            int k0 = ks * 8;
            float a[4];
            a[0] = Ps[k0 + tig][mq0];
            a[1] = Ps[k0 + tig][mq1];
            a[2] = Ps[k0 + tig + 4][mq0];
            a[3] = Ps[k0 + tig + 4][mq1];
#pragma unroll
            for (int nt = 0; nt < 8; nt++) {
                float bf[2];
                bf[0] = Vs[k0 + tig][nt * 8 + gid];
                bf[1] = Vs[k0 + tig + 4][nt * 8 + gid];
                mma8(Oacc[nt], a, bf);
            }
        }
        __syncthreads();
    }

    // finalize: quad-reduce row sums (all quad lanes end with the total)
    rs0 += __shfl_xor_sync(0xffffffffu, rs0, 1);
    rs0 += __shfl_xor_sync(0xffffffffu, rs0, 2);
    rs1 += __shfl_xor_sync(0xffffffffu, rs1, 1);
    rs1 += __shfl_xor_sync(0xffffffffu, rs1, 2);
    float inv0 = 1.0f / rs0, inv1 = 1.0f / rs1;
    const int r0 = q0 + mq0, r1 = q0 + mq1;
    float* c0p = g_concat + ((size_t)b * SQ + r0) * DM + h * DK;
    float* c1p = g_concat + ((size_t)b * SQ + r1) * DM + h * DK;
#pragma unroll
    for (int nt = 0; nt < 8; nt++) {
        int cl = nt * 8 + 2 * tig;
        *(float2*)(c0p + cl) = make_float2(Oacc[nt][0] * inv0, Oacc[nt][1] * inv0);
        *(float2*)(c1p + cl) = make_float2(Oacc[nt][2] * inv1, Oacc[nt][3] * inv1);
    }
}

// ---------------------------------------------------------------------------
// Kernel 3: out = concat @ Wo  (4096x1024x1024), tf32 MMA, BM=BN=128, BK=32.
// ---------------------------------------------------------------------------
__global__ __launch_bounds__(256) void outproj_mma(
    const float* __restrict__ Wo, float* __restrict__ out)
{
    const int row0 = blockIdx.x * 128;
    const int col0 = blockIdx.y * 128;

    __shared__ float As[32][136];
    __shared__ float Bs[32][136];

    const int t    = threadIdx.x;
    const int warp = t >> 5, lane = t & 31;
    const int gid  = lane >> 2, tig = lane & 3;
    const int mb   = (warp >> 1) * 32;
    const int nb   = (warp & 1) * 64;

    float acc[2][8][4] = {};

    for (int kt = 0; kt < DM; kt += 32) {
#pragma unroll
        for (int u = 0; u < 4; u++) {
            int idx = t + u * 256;
            int row = idx & 127, k4 = idx >> 7;
            float4 a = *(const float4*)(g_concat + (size_t)(row0 + row) * DM + kt + k4 * 4);
            As[k4 * 4 + 0][row] = f2tf(a.x);
            As[k4 * 4 + 1][row] = f2tf(a.y);
            As[k4 * 4 + 2][row] = f2tf(a.z);
            As[k4 * 4 + 3][row] = f2tf(a.w);
        }
#pragma unroll
        for (int u = 0; u < 4; u++) {
            int idx = t + u * 256;
            int k = idx >> 5, c4 = idx & 31;
            float4 bv = *(const float4*)(Wo + (size_t)(kt + k) * DM + col0 + c4 * 4);
            *(float4*)&Bs[k][c4 * 4] = make_float4(f2tf(bv.x), f2tf(bv.y), f2tf(bv.z), f2tf(bv.w));
        }
        __syncthreads();
#pragma unroll
        for (int ks = 0; ks < 4; ks++) {
            const int k0 = ks * 8;
            float a[2][4], b[8][2];
#pragma unroll
            for (int mt = 0; mt < 2; mt++) {
                int m = mb + mt * 16 + gid;
                a[mt][0] = As[k0 + tig][m];
                a[mt][1] = As[k0 + tig][m + 8];
                a[mt][2] = As[k0 + tig + 4][m];
                a[mt][3] = As[k0 + tig + 4][m + 8];
            }
#pragma unroll
            for (int nt = 0; nt < 8; nt++) {
                int n = nb + nt * 8 + gid;
                b[nt][0] = Bs[k0 + tig][n];
                b[nt][1] = Bs[k0 + tig + 4][n];
            }
#pragma unroll
            for (int mt = 0; mt < 2; mt++)
#pragma unroll
                for (int nt = 0; nt < 8; nt++) mma8(acc[mt][nt], a[mt], b[nt]);
        }
        __syncthreads();
    }
#pragma unroll
    for (int mt = 0; mt < 2; mt++) {
        int r = row0 + mb + mt * 16 + gid;
#pragma unroll
        for (int nt = 0; nt < 8; nt++) {
            int col = col0 + nb + nt * 8 + 2 * tig;
            *(float2*)(out + (size_t)r * DM + col)       = make_float2(acc[mt][nt][0], acc[mt][nt][1]);
            *(float2*)(out + (size_t)(r + 8) * DM + col) = make_float2(acc[mt][nt][2], acc[mt][nt][3]);
        }
    }
}

// ---------------------------------------------------------------------------
extern "C" void kernel_launch(void* const* d_in, const int* in_sizes, int n_in,
                              void* d_out, int out_size)
{
    const float* q    = (const float*)d_in[0];
    const float* k    = (const float*)d_in[1];
    const float* v    = (const float*)d_in[2];
    const int*   mask = (const int*)  d_in[3];
    const float* Wq   = (const float*)d_in[4];
    const float* Wk   = (const float*)d_in[5];
    const float* Wv   = (const float*)d_in[6];
    const float* Wo   = (const float*)d_in[7];

    float* out = (float*)d_out;                 // [B,S,DM]
    float* scp = out + (size_t)MR * DM;         // masked scores [H,B,S,S]

    static int smem_set = 0;
    if (!smem_set) {
        cudaFuncSetAttribute(attn_mma, cudaFuncAttributeMaxDynamicSharedMemorySize, 176128);
        smem_set = 1;
    }

    proj_mma   <<<dim3(32, 8, 3), 256>>>(q, k, v, Wq, Wk, Wv);
    attn_mma   <<<dim3(8, 64), 256, 176128>>>(mask, scp);
    outproj_mma<<<dim3(32, 8), 256>>>(Wo, out);
}

// round 5
// speedup vs baseline: 2.3362x; 1.2398x over previous
#include <cuda_runtime.h>
#include <cstdint>

#define NH 16
#define NB 4
#define SQ 1024
#define DM 1024
#define DK 64
#define MR (NB * SQ)
#define HB (NH * NB)

__device__ float g_q[(size_t)HB * SQ * DK];
__device__ float g_k[(size_t)HB * SQ * DK];
__device__ float g_v[(size_t)HB * SQ * DK];
__device__ float g_concat[(size_t)MR * DM];

__device__ __forceinline__ float f2tf(float x) {
    unsigned u;
    asm("cvt.rna.tf32.f32 %0, %1;" : "=r"(u) : "f"(x));
    return __uint_as_float(u);
}

__device__ __forceinline__ void mma8(float* d, const float* a, const float* b) {
    asm volatile(
        "mma.sync.aligned.m16n8k8.row.col.f32.tf32.tf32.f32 "
        "{%0,%1,%2,%3}, {%4,%5,%6,%7}, {%8,%9}, {%0,%1,%2,%3};\n"
        : "+f"(d[0]), "+f"(d[1]), "+f"(d[2]), "+f"(d[3])
        : "r"(__float_as_uint(a[0])), "r"(__float_as_uint(a[1])),
          "r"(__float_as_uint(a[2])), "r"(__float_as_uint(a[3])),
          "r"(__float_as_uint(b[0])), "r"(__float_as_uint(b[1])));
}

__device__ __forceinline__ void cp16(uint32_t dst, const void* src) {
    asm volatile("cp.async.cg.shared.global [%0], [%1], 16;" :: "r"(dst), "l"(src));
}
__device__ __forceinline__ void cp_commit() { asm volatile("cp.async.commit_group;"); }
__device__ __forceinline__ void cp_wait0() { asm volatile("cp.async.wait_group 0;"); }

// ---------------------------------------------------------------------------
// Kernel 1: per-head projections. BM=128 BN=128 BK=16, 2-stage cp.async.
// cp.async copies RAW fp32; fragments are RNA-rounded to tf32 in registers
// right after the LDS load (mma.tf32 would otherwise TRUNCATE -> R4 failure).
// ---------------------------------------------------------------------------
__global__ __launch_bounds__(256) void proj_mma(
    const float* __restrict__ Xq, const float* __restrict__ Xk, const float* __restrict__ Xv,
    const float* __restrict__ Wq, const float* __restrict__ Wk, const float* __restrict__ Wv)
{
    const int which = blockIdx.z;
    const float* X = (which == 0) ? Xq : (which == 1) ? Xk : Xv;
    const float* W = (which == 0) ? Wq : (which == 1) ? Wk : Wv;
    float* O       = (which == 0) ? g_q : (which == 1) ? g_k : g_v;
    const int row0 = blockIdx.x * 128;
    const int col0 = blockIdx.y * 128;

    __shared__ __align__(16) float As[2][128 * 20];
    __shared__ __align__(16) float Bs[2][16 * 136];
    const uint32_t sA = (uint32_t)__cvta_generic_to_shared(&As[0][0]);
    const uint32_t sB = (uint32_t)__cvta_generic_to_shared(&Bs[0][0]);
    const uint32_t ASZ = 128 * 20 * 4, BSZ = 16 * 136 * 4;

    const int t    = threadIdx.x;
    const int warp = t >> 5, lane = t & 31;
    const int gid  = lane >> 2, tig = lane & 3;
    const int mb   = (warp >> 1) * 32;
    const int nb   = (warp & 1) * 64;

    const float* aptr[2]; uint32_t aoff[2];
    const float* bptr[2]; uint32_t boff[2];
#pragma unroll
    for (int u = 0; u < 2; u++) {
        int c = t + u * 256;
        int row = c >> 2, k4 = c & 3;
        aptr[u] = X + (size_t)(row0 + row) * DM + k4 * 4;
        aoff[u] = (row * 20 + k4 * 4) * 4;
        int d = c >> 5, c4 = c & 31;
        int col = col0 + c4 * 4, h = col >> 6, kk = col & 63;
        bptr[u] = W + (size_t)h * DM * DK + (size_t)d * DK + kk;
        boff[u] = (d * 136 + c4 * 4) * 4;
    }

    float acc[2][8][4] = {};

#pragma unroll
    for (int u = 0; u < 2; u++) {
        cp16(sA + aoff[u], aptr[u]);
        cp16(sB + boff[u], bptr[u]);
    }
    cp_commit();

    for (int tt = 0; tt < 64; tt++) {
        const int slot = tt & 1;
        cp_wait0();
        __syncthreads();
        if (tt + 1 < 64) {
            const int kt = (tt + 1) * 16;
            const int so = slot ^ 1;
#pragma unroll
            for (int u = 0; u < 2; u++) {
                cp16(sA + so * ASZ + aoff[u], aptr[u] + kt);
                cp16(sB + so * BSZ + boff[u], bptr[u] + (size_t)kt * DK);
            }
        }
        cp_commit();

        const float* Ap = As[slot];
        const float* Bp = Bs[slot];
#pragma unroll
        for (int ks = 0; ks < 16; ks += 8) {
            float a[2][4], bf[8][2];
#pragma unroll
            for (int mt = 0; mt < 2; mt++) {
                int m = mb + mt * 16 + gid;
                a[mt][0] = f2tf(Ap[m * 20 + ks + tig]);
                a[mt][1] = f2tf(Ap[(m + 8) * 20 + ks + tig]);
                a[mt][2] = f2tf(Ap[m * 20 + ks + tig + 4]);
                a[mt][3] = f2tf(Ap[(m + 8) * 20 + ks + tig + 4]);
            }
#pragma unroll
            for (int nt = 0; nt < 8; nt++) {
                int n = nb + nt * 8 + gid;
                bf[nt][0] = f2tf(Bp[(ks + tig) * 136 + n]);
                bf[nt][1] = f2tf(Bp[(ks + tig + 4) * 136 + n]);
            }
#pragma unroll
            for (int mt = 0; mt < 2; mt++)
#pragma unroll
                for (int nt = 0; nt < 8; nt++) mma8(acc[mt][nt], a[mt], bf[nt]);
        }
    }

#pragma unroll
    for (int mt = 0; mt < 2; mt++) {
        int r0 = row0 + mb + mt * 16 + gid;
        int bb = r0 >> 10, s0 = r0 & 1023;
#pragma unroll
        for (int nt = 0; nt < 8; nt++) {
            int col = col0 + nb + nt * 8 + 2 * tig;
            int h = col >> 6, kk = col & 63;
            float* base = O + (size_t)(h * NB + bb) * SQ * DK;
            *(float2*)(base + (size_t)s0 * DK + kk) =
                make_float2(f2tf(acc[mt][nt][0]), f2tf(acc[mt][nt][1]));
            *(float2*)(base + (size_t)(s0 + 8) * DK + kk) =
                make_float2(f2tf(acc[mt][nt][2]), f2tf(acc[mt][nt][3]));
        }
    }
}

// ---------------------------------------------------------------------------
// Kernel 2: fused attention. CTA = (hb, 128 q), 16 key tiles of 64.
// All inputs (g_q/g_k/g_v, Ps) are producer-side tf32-rounded -> no cvt here.
// ---------------------------------------------------------------------------
__global__ __launch_bounds__(256) void attn_mma(
    const int* __restrict__ mask, float* __restrict__ sc)
{
    extern __shared__ float sm[];
    float* Qs   = sm;                    // [128][68]
    float* Ps   = Qs + 128 * 68;         // [128][68]  (64 key cols + pad)
    float* Ksm  = Ps + 128 * 68;         // [2][64][68]
    float* Vsm  = Ksm + 2 * 64 * 68;     // [2][64][68]
    float* rsum = Vsm + 2 * 64 * 68;     // [128]

    const uint32_t qsm = (uint32_t)__cvta_generic_to_shared(Qs);
    const uint32_t ksm = (uint32_t)__cvta_generic_to_shared(Ksm);
    const uint32_t vsm = (uint32_t)__cvta_generic_to_shared(Vsm);
    const uint32_t TSZ = 64 * 68 * 4;

    const int hb = blockIdx.y;
    const int h  = hb >> 2, b = hb & 3;
    const int q0 = blockIdx.x * 128;
    const int t = threadIdx.x, warp = t >> 5, lane = t & 31;
    const int gid = lane >> 2, tig = lane & 3;
    const int wm = warp >> 1, wn = warp & 1;

    const float* qbase = g_q + ((size_t)hb * SQ + q0) * DK;
    const float* kbase = g_k + (size_t)hb * SQ * DK;
    const float* vbase = g_v + (size_t)hb * SQ * DK;

    if (t < 128) rsum[t] = 0.f;

#pragma unroll
    for (int u = 0; u < 8; u++) {
        int c = t + u * 256;
        int row = c >> 4, c4 = c & 15;
        cp16(qsm + (row * 68 + c4 * 4) * 4, qbase + (size_t)row * DK + c4 * 4);
    }
#pragma unroll
    for (int u = 0; u < 4; u++) {
        int c = t + u * 256;
        int row = c >> 4, c4 = c & 15;
        cp16(ksm + (row * 68 + c4 * 4) * 4, kbase + (size_t)row * DK + c4 * 4);
        cp16(vsm + (row * 68 + c4 * 4) * 4, vbase + (size_t)row * DK + c4 * 4);
    }
    cp_commit();

    float Oacc[2][4][4] = {};
    float rs[2][2] = {};
    const float NEGINF = __int_as_float(0xff800000u);

    for (int kb = 0; kb < 16; kb++) {
        const int slot = kb & 1;
        cp_wait0();
        __syncthreads();
        if (kb + 1 < 16) {
            const int so = slot ^ 1;
            const float* kp = kbase + (size_t)(kb + 1) * 64 * DK;
            const float* vp = vbase + (size_t)(kb + 1) * 64 * DK;
#pragma unroll
            for (int u = 0; u < 4; u++) {
                int c = t + u * 256;
                int row = c >> 4, c4 = c & 15;
                cp16(ksm + so * TSZ + (row * 68 + c4 * 4) * 4, kp + (size_t)row * DK + c4 * 4);
                cp16(vsm + so * TSZ + (row * 68 + c4 * 4) * 4, vp + (size_t)row * DK + c4 * 4);
            }
        }
        cp_commit();

        const float* Kp = Ksm + slot * 64 * 68;
        const float* Vp = Vsm + slot * 64 * 68;

        // S = Q @ K^T : warp tile 32q x 32key
        float Sacc[2][4][4] = {};
#pragma unroll
        for (int ks = 0; ks < 8; ks++) {
            int k0 = ks * 8;
            float a[2][4];
#pragma unroll
            for (int mt = 0; mt < 2; mt++) {
                int m = wm * 32 + mt * 16 + gid;
                a[mt][0] = Qs[m * 68 + k0 + tig];
                a[mt][1] = Qs[(m + 8) * 68 + k0 + tig];
                a[mt][2] = Qs[m * 68 + k0 + tig + 4];
                a[mt][3] = Qs[(m + 8) * 68 + k0 + tig + 4];
            }
#pragma unroll
            for (int nt = 0; nt < 4; nt++) {
                int n = wn * 32 + nt * 8 + gid;
                float bf[2];
                bf[0] = Kp[n * 68 + k0 + tig];
                bf[1] = Kp[n * 68 + k0 + tig + 4];
                mma8(Sacc[0][nt], a[0], bf);
                mma8(Sacc[1][nt], a[1], bf);
            }
        }

        // scale, mask, write scores to d_out, exp -> Ps(tf32) + row sums
#pragma unroll
        for (int mt = 0; mt < 2; mt++) {
            int rl0 = wm * 32 + mt * 16 + gid;
            int rl1 = rl0 + 8;
            const int* mr0 = mask + ((size_t)b * SQ + q0 + rl0) * SQ + kb * 64 + wn * 32;
            const int* mr1 = mask + ((size_t)b * SQ + q0 + rl1) * SQ + kb * 64 + wn * 32;
            float* sr0 = sc + ((size_t)hb * SQ + q0 + rl0) * SQ + kb * 64 + wn * 32;
            float* sr1 = sc + ((size_t)hb * SQ + q0 + rl1) * SQ + kb * 64 + wn * 32;
#pragma unroll
            for (int nt = 0; nt < 4; nt++) {
                int cl = nt * 8 + 2 * tig;
                int2 m0 = *(const int2*)(mr0 + cl);
                int2 m1 = *(const int2*)(mr1 + cl);
                float s00 = m0.x ? Sacc[mt][nt][0] * 0.125f : NEGINF;
                float s01 = m0.y ? Sacc[mt][nt][1] * 0.125f : NEGINF;
                float s10 = m1.x ? Sacc[mt][nt][2] * 0.125f : NEGINF;
                float s11 = m1.y ? Sacc[mt][nt][3] * 0.125f : NEGINF;
                *(float2*)(sr0 + cl) = make_float2(s00, s01);
                *(float2*)(sr1 + cl) = make_float2(s10, s11);
                float e00 = __expf(s00), e01 = __expf(s01);
                float e10 = __expf(s10), e11 = __expf(s11);
                rs[mt][0] += e00 + e01;
                rs[mt][1] += e10 + e11;
                int pc = wn * 32 + cl;
                *(float2*)&Ps[rl0 * 68 + pc] = make_float2(f2tf(e00), f2tf(e01));
                *(float2*)&Ps[rl1 * 68 + pc] = make_float2(f2tf(e10), f2tf(e11));
            }
        }
        __syncthreads();

        // O += P @ V : warp tile 32q x 32dk, k = 64 keys
#pragma unroll
        for (int ks = 0; ks < 8; ks++) {
            int k0 = ks * 8;
            float a[2][4];
#pragma unroll
            for (int mt = 0; mt < 2; mt++) {
                int m = wm * 32 + mt * 16 + gid;
                a[mt][0] = Ps[m * 68 + k0 + tig];
                a[mt][1] = Ps[(m + 8) * 68 + k0 + tig];
                a[mt][2] = Ps[m * 68 + k0 + tig + 4];
                a[mt][3] = Ps[(m + 8) * 68 + k0 + tig + 4];
            }
#pragma unroll
            for (int nt = 0; nt < 4; nt++) {
                int n = wn * 32 + nt * 8 + gid;
                float bf[2];
                bf[0] = Vp[(k0 + tig) * 68 + n];
                bf[1] = Vp[(k0 + tig + 4) * 68 + n];
                mma8(Oacc[0][nt], a[0], bf);
                mma8(Oacc[1][nt], a[1], bf);
            }
        }
    }

    // reduce row sums across quad lanes, then across the two wn warps
#pragma unroll
    for (int mt = 0; mt < 2; mt++)
#pragma unroll
        for (int hh = 0; hh < 2; hh++) {
            float v = rs[mt][hh];
            v += __shfl_xor_sync(0xffffffffu, v, 1);
            v += __shfl_xor_sync(0xffffffffu, v, 2);
            if (tig == 0) atomicAdd(&rsum[wm * 32 + mt * 16 + hh * 8 + gid], v);
        }
    __syncthreads();

#pragma unroll
    for (int mt = 0; mt < 2; mt++) {
        int rl0 = wm * 32 + mt * 16 + gid;
        int rl1 = rl0 + 8;
        float inv0 = 1.0f / rsum[rl0];
        float inv1 = 1.0f / rsum[rl1];
        float* c0 = g_concat + ((size_t)b * SQ + q0 + rl0) * DM + h * DK + wn * 32;
        float* c1 = g_concat + ((size_t)b * SQ + q0 + rl1) * DM + h * DK + wn * 32;
#pragma unroll
        for (int nt = 0; nt < 4; nt++) {
            int cl = nt * 8 + 2 * tig;
            *(float2*)(c0 + cl) = make_float2(f2tf(Oacc[mt][nt][0] * inv0), f2tf(Oacc[mt][nt][1] * inv0));
            *(float2*)(c1 + cl) = make_float2(f2tf(Oacc[mt][nt][2] * inv1), f2tf(Oacc[mt][nt][3] * inv1));
        }
    }
}

// ---------------------------------------------------------------------------
// Kernel 3: out = concat @ Wo. A (g_concat) is pre-rounded tf32; Wo fragments
// are RNA-rounded in registers. fp32 output stores.
// ---------------------------------------------------------------------------
__global__ __launch_bounds__(256) void outproj_mma(
    const float* __restrict__ Wo, float* __restrict__ out)
{
    const int row0 = blockIdx.x * 128;
    const int col0 = blockIdx.y * 128;

    __shared__ __align__(16) float As[2][128 * 20];
    __shared__ __align__(16) float Bs[2][16 * 136];
    const uint32_t sA = (uint32_t)__cvta_generic_to_shared(&As[0][0]);
    const uint32_t sB = (uint32_t)__cvta_generic_to_shared(&Bs[0][0]);
    const uint32_t ASZ = 128 * 20 * 4, BSZ = 16 * 136 * 4;

    const int t    = threadIdx.x;
    const int warp = t >> 5, lane = t & 31;
    const int gid  = lane >> 2, tig = lane & 3;
    const int mb   = (warp >> 1) * 32;
    const int nb   = (warp & 1) * 64;

    const float* aptr[2]; uint32_t aoff[2];
    const float* bptr[2]; uint32_t boff[2];
#pragma unroll
    for (int u = 0; u < 2; u++) {
        int c = t + u * 256;
        int row = c >> 2, k4 = c & 3;
        aptr[u] = g_concat + (size_t)(row0 + row) * DM + k4 * 4;
        aoff[u] = (row * 20 + k4 * 4) * 4;
        int d = c >> 5, c4 = c & 31;
        bptr[u] = Wo + (size_t)d * DM + col0 + c4 * 4;
        boff[u] = (d * 136 + c4 * 4) * 4;
    }

    float acc[2][8][4] = {};

#pragma unroll
    for (int u = 0; u < 2; u++) {
        cp16(sA + aoff[u], aptr[u]);
        cp16(sB + boff[u], bptr[u]);
    }
    cp_commit();

    for (int tt = 0; tt < 64; tt++) {
        const int slot = tt & 1;
        cp_wait0();
        __syncthreads();
        if (tt + 1 < 64) {
            const int kt = (tt + 1) * 16;
            const int so = slot ^ 1;
#pragma unroll
            for (int u = 0; u < 2; u++) {
                cp16(sA + so * ASZ + aoff[u], aptr[u] + kt);
                cp16(sB + so * BSZ + boff[u], bptr[u] + (size_t)kt * DM);
            }
        }
        cp_commit();

        const float* Ap = As[slot];
        const float* Bp = Bs[slot];
#pragma unroll
        for (int ks = 0; ks < 16; ks += 8) {
            float a[2][4], bf[8][2];
#pragma unroll
            for (int mt = 0; mt < 2; mt++) {
                int m = mb + mt * 16 + gid;
                a[mt][0] = Ap[m * 20 + ks + tig];
                a[mt][1] = Ap[(m + 8) * 20 + ks + tig];
                a[mt][2] = Ap[m * 20 + ks + tig + 4];
                a[mt][3] = Ap[(m + 8) * 20 + ks + tig + 4];
            }
#pragma unroll
            for (int nt = 0; nt < 8; nt++) {
                int n = nb + nt * 8 + gid;
                bf[nt][0] = f2tf(Bp[(ks + tig) * 136 + n]);
                bf[nt][1] = f2tf(Bp[(ks + tig + 4) * 136 + n]);
            }
#pragma unroll
            for (int mt = 0; mt < 2; mt++)
#pragma unroll
                for (int nt = 0; nt < 8; nt++) mma8(acc[mt][nt], a[mt], bf[nt]);
        }
    }

#pragma unroll
    for (int mt = 0; mt < 2; mt++) {
        int r = row0 + mb + mt * 16 + gid;
#pragma unroll
        for (int nt = 0; nt < 8; nt++) {
            int col = col0 + nb + nt * 8 + 2 * tig;
            *(float2*)(out + (size_t)r * DM + col)       = make_float2(acc[mt][nt][0], acc[mt][nt][1]);
            *(float2*)(out + (size_t)(r + 8) * DM + col) = make_float2(acc[mt][nt][2], acc[mt][nt][3]);
        }
    }
}

// ---------------------------------------------------------------------------
extern "C" void kernel_launch(void* const* d_in, const int* in_sizes, int n_in,
                              void* d_out, int out_size)
{
    const float* q    = (const float*)d_in[0];
    const float* k    = (const float*)d_in[1];
    const float* v    = (const float*)d_in[2];
    const int*   mask = (const int*)  d_in[3];
    const float* Wq   = (const float*)d_in[4];
    const float* Wk   = (const float*)d_in[5];
    const float* Wv   = (const float*)d_in[6];
    const float* Wo   = (const float*)d_in[7];

    float* out = (float*)d_out;
    float* scp = out + (size_t)MR * DM;

    static int smem_set = 0;
    if (!smem_set) {
        cudaFuncSetAttribute(attn_mma, cudaFuncAttributeMaxDynamicSharedMemorySize, 139776);
        smem_set = 1;
    }

    proj_mma   <<<dim3(32, 8, 3), 256>>>(q, k, v, Wq, Wk, Wv);
    attn_mma   <<<dim3(8, 64), 256, 139776>>>(mask, scp);
    outproj_mma<<<dim3(32, 8), 256>>>(Wo, out);
}

// round 6
// speedup vs baseline: 2.5022x; 1.0710x over previous
#include <cuda_runtime.h>
#include <cstdint>

#define NH 16
#define NB 4
#define SQ 1024
#define DM 1024
#define DK 64
#define MR (NB * SQ)
#define HB (NH * NB)

// Scratch (__device__ globals per allocation-free rule)
__device__ float g_q[(size_t)HB * SQ * DK];
__device__ float g_k[(size_t)HB * SQ * DK];
__device__ float g_v[(size_t)HB * SQ * DK];
__device__ float g_concat[(size_t)MR * DM];
// tf32-pre-rounded inputs
__device__ float g_xq[(size_t)MR * DM];
__device__ float g_xk[(size_t)MR * DM];
__device__ float g_xv[(size_t)MR * DM];
__device__ float g_wq[(size_t)NH * DM * DK];
__device__ float g_wk[(size_t)NH * DM * DK];
__device__ float g_wv[(size_t)NH * DM * DK];
__device__ float g_wo[(size_t)NH * DK * DM];

__device__ __forceinline__ float f2tf(float x) {
    unsigned u;
    asm("cvt.rna.tf32.f32 %0, %1;" : "=r"(u) : "f"(x));
    return __uint_as_float(u);
}

__device__ __forceinline__ void mma8(float* d, const float* a, const float* b) {
    asm volatile(
        "mma.sync.aligned.m16n8k8.row.col.f32.tf32.tf32.f32 "
        "{%0,%1,%2,%3}, {%4,%5,%6,%7}, {%8,%9}, {%0,%1,%2,%3};\n"
        : "+f"(d[0]), "+f"(d[1]), "+f"(d[2]), "+f"(d[3])
        : "r"(__float_as_uint(a[0])), "r"(__float_as_uint(a[1])),
          "r"(__float_as_uint(a[2])), "r"(__float_as_uint(a[3])),
          "r"(__float_as_uint(b[0])), "r"(__float_as_uint(b[1])));
}

__device__ __forceinline__ void cp16(uint32_t dst, const void* src) {
    asm volatile("cp.async.cg.shared.global [%0], [%1], 16;" :: "r"(dst), "l"(src));
}
__device__ __forceinline__ void cp_commit() { asm volatile("cp.async.commit_group;"); }
__device__ __forceinline__ void cp_wait0() { asm volatile("cp.async.wait_group 0;"); }
__device__ __forceinline__ void cp_wait1() { asm volatile("cp.async.wait_group 1;"); }

// ---------------------------------------------------------------------------
// Kernel 0: elementwise tf32 pre-rounding (vectorized).
// ---------------------------------------------------------------------------
__global__ __launch_bounds__(256) void prep_round(
    const float* __restrict__ src, float* __restrict__ dst)
{
    int i = blockIdx.x * 256 + threadIdx.x;
    float4 a = *(const float4*)(src + (size_t)i * 4);
    *(float4*)(dst + (size_t)i * 4) =
        make_float4(f2tf(a.x), f2tf(a.y), f2tf(a.z), f2tf(a.w));
}

// ---------------------------------------------------------------------------
// Kernel 1: per-head projections. BM=128 BN=128 BK=32, 3-stage cp.async,
// no cvts in the hot loop (inputs pre-rounded).
// ---------------------------------------------------------------------------
__global__ __launch_bounds__(256) void proj_mma()
{
    const int which = blockIdx.z;
    const float* X = (which == 0) ? g_xq : (which == 1) ? g_xk : g_xv;
    const float* W = (which == 0) ? g_wq : (which == 1) ? g_wk : g_wv;
    float* O       = (which == 0) ? g_q  : (which == 1) ? g_k  : g_v;
    const int row0 = blockIdx.x * 128;
    const int col0 = blockIdx.y * 128;

    extern __shared__ __align__(16) float sh[];
    float* As = sh;                  // [3][128*36]
    float* Bs = sh + 3 * 128 * 36;   // [3][32*136]
    const uint32_t sA = (uint32_t)__cvta_generic_to_shared(As);
    const uint32_t sB = (uint32_t)__cvta_generic_to_shared(Bs);
    const uint32_t ASZ = 128 * 36 * 4, BSZ = 32 * 136 * 4;

    const int t    = threadIdx.x;
    const int warp = t >> 5, lane = t & 31;
    const int gid  = lane >> 2, tig = lane & 3;
    const int mb   = (warp >> 1) * 32;
    const int nb   = (warp & 1) * 64;

    const float* aptr[4]; uint32_t aoff[4];
    const float* bptr[4]; uint32_t boff[4];
#pragma unroll
    for (int u = 0; u < 4; u++) {
        int c = t + u * 256;
        int arow = c >> 3, k4 = c & 7;           // A: 128 x 32
        aptr[u] = X + (size_t)(row0 + arow) * DM + k4 * 4;
        aoff[u] = (arow * 36 + k4 * 4) * 4;
        int brow = c >> 5, c4 = c & 31;          // B: 32 x 128
        int col = col0 + c4 * 4, h = col >> 6, kk = col & 63;
        bptr[u] = W + (size_t)h * DM * DK + (size_t)brow * DK + kk;
        boff[u] = (brow * 136 + c4 * 4) * 4;
    }

    float acc[2][8][4] = {};
    const int NT = 32;   // 1024 / 32

    // prologue: tiles 0 and 1
#pragma unroll
    for (int p = 0; p < 2; p++) {
#pragma unroll
        for (int u = 0; u < 4; u++) {
            cp16(sA + p * ASZ + aoff[u], aptr[u] + p * 32);
            cp16(sB + p * BSZ + boff[u], bptr[u] + (size_t)(p * 32) * DK);
        }
        cp_commit();
    }

    int slot = 0;
    for (int tt = 0; tt < NT; tt++) {
        cp_wait1();
        __syncthreads();
        if (tt + 2 < NT) {
            const int ps = (tt + 2) % 3;
            const int kt = (tt + 2) * 32;
#pragma unroll
            for (int u = 0; u < 4; u++) {
                cp16(sA + ps * ASZ + aoff[u], aptr[u] + kt);
                cp16(sB + ps * BSZ + boff[u], bptr[u] + (size_t)kt * DK);
            }
        }
        cp_commit();

        const float* Ap = As + slot * 128 * 36;
        const float* Bp = Bs + slot * 32 * 136;
#pragma unroll
        for (int ks = 0; ks < 32; ks += 8) {
            float a[2][4], bf[8][2];
#pragma unroll
            for (int mt = 0; mt < 2; mt++) {
                int m = mb + mt * 16 + gid;
                a[mt][0] = Ap[m * 36 + ks + tig];
                a[mt][1] = Ap[(m + 8) * 36 + ks + tig];
                a[mt][2] = Ap[m * 36 + ks + tig + 4];
                a[mt][3] = Ap[(m + 8) * 36 + ks + tig + 4];
            }
#pragma unroll
            for (int nt = 0; nt < 8; nt++) {
                int n = nb + nt * 8 + gid;
                bf[nt][0] = Bp[(ks + tig) * 136 + n];
                bf[nt][1] = Bp[(ks + tig + 4) * 136 + n];
            }
#pragma unroll
            for (int mt = 0; mt < 2; mt++)
#pragma unroll
                for (int nt = 0; nt < 8; nt++) mma8(acc[mt][nt], a[mt], bf[nt]);
        }
        slot = (slot + 1 == 3) ? 0 : slot + 1;
    }

#pragma unroll
    for (int mt = 0; mt < 2; mt++) {
        int r0 = row0 + mb + mt * 16 + gid;
        int bb = r0 >> 10, s0 = r0 & 1023;
#pragma unroll
        for (int nt = 0; nt < 8; nt++) {
            int col = col0 + nb + nt * 8 + 2 * tig;
            int h = col >> 6, kk = col & 63;
            float* base = O + (size_t)(h * NB + bb) * SQ * DK;
            *(float2*)(base + (size_t)s0 * DK + kk) =
                make_float2(f2tf(acc[mt][nt][0]), f2tf(acc[mt][nt][1]));
            *(float2*)(base + (size_t)(s0 + 8) * DK + kk) =
                make_float2(f2tf(acc[mt][nt][2]), f2tf(acc[mt][nt][3]));
        }
    }
}

// ---------------------------------------------------------------------------
// Kernel 2: fused attention (unchanged from R5 — correct & producer-rounded).
// ---------------------------------------------------------------------------
__global__ __launch_bounds__(256) void attn_mma(
    const int* __restrict__ mask, float* __restrict__ sc)
{
    extern __shared__ float sm[];
    float* Qs   = sm;                    // [128][68]
    float* Ps   = Qs + 128 * 68;         // [128][68]
    float* Ksm  = Ps + 128 * 68;         // [2][64][68]
    float* Vsm  = Ksm + 2 * 64 * 68;     // [2][64][68]
    float* rsum = Vsm + 2 * 64 * 68;     // [128]

    const uint32_t qsm = (uint32_t)__cvta_generic_to_shared(Qs);
    const uint32_t ksm = (uint32_t)__cvta_generic_to_shared(Ksm);
    const uint32_t vsm = (uint32_t)__cvta_generic_to_shared(Vsm);
    const uint32_t TSZ = 64 * 68 * 4;

    const int hb = blockIdx.y;
    const int h  = hb >> 2, b = hb & 3;
    const int q0 = blockIdx.x * 128;
    const int t = threadIdx.x, warp = t >> 5, lane = t & 31;
    const int gid = lane >> 2, tig = lane & 3;
    const int wm = warp >> 1, wn = warp & 1;

    const float* qbase = g_q + ((size_t)hb * SQ + q0) * DK;
    const float* kbase = g_k + (size_t)hb * SQ * DK;
    const float* vbase = g_v + (size_t)hb * SQ * DK;

    if (t < 128) rsum[t] = 0.f;

#pragma unroll
    for (int u = 0; u < 8; u++) {
        int c = t + u * 256;
        int row = c >> 4, c4 = c & 15;
        cp16(qsm + (row * 68 + c4 * 4) * 4, qbase + (size_t)row * DK + c4 * 4);
    }
#pragma unroll
    for (int u = 0; u < 4; u++) {
        int c = t + u * 256;
        int row = c >> 4, c4 = c & 15;
        cp16(ksm + (row * 68 + c4 * 4) * 4, kbase + (size_t)row * DK + c4 * 4);
        cp16(vsm + (row * 68 + c4 * 4) * 4, vbase + (size_t)row * DK + c4 * 4);
    }
    cp_commit();

    float Oacc[2][4][4] = {};
    float rs[2][2] = {};
    const float NEGINF = __int_as_float(0xff800000u);

    for (int kb = 0; kb < 16; kb++) {
        const int slot = kb & 1;
        cp_wait0();
        __syncthreads();
        if (kb + 1 < 16) {
            const int so = slot ^ 1;
            const float* kp = kbase + (size_t)(kb + 1) * 64 * DK;
            const float* vp = vbase + (size_t)(kb + 1) * 64 * DK;
#pragma unroll
            for (int u = 0; u < 4; u++) {
                int c = t + u * 256;
                int row = c >> 4, c4 = c & 15;
                cp16(ksm + so * TSZ + (row * 68 + c4 * 4) * 4, kp + (size_t)row * DK + c4 * 4);
                cp16(vsm + so * TSZ + (row * 68 + c4 * 4) * 4, vp + (size_t)row * DK + c4 * 4);
            }
        }
        cp_commit();

        const float* Kp = Ksm + slot * 64 * 68;
        const float* Vp = Vsm + slot * 64 * 68;

        float Sacc[2][4][4] = {};
#pragma unroll
        for (int ks = 0; ks < 8; ks++) {
            int k0 = ks * 8;
            float a[2][4];
#pragma unroll
            for (int mt = 0; mt < 2; mt++) {
                int m = wm * 32 + mt * 16 + gid;
                a[mt][0] = Qs[m * 68 + k0 + tig];
                a[mt][1] = Qs[(m + 8) * 68 + k0 + tig];
                a[mt][2] = Qs[m * 68 + k0 + tig + 4];
                a[mt][3] = Qs[(m + 8) * 68 + k0 + tig + 4];
            }
#pragma unroll
            for (int nt = 0; nt < 4; nt++) {
                int n = wn * 32 + nt * 8 + gid;
                float bf[2];
                bf[0] = Kp[n * 68 + k0 + tig];
                bf[1] = Kp[n * 68 + k0 + tig + 4];
                mma8(Sacc[0][nt], a[0], bf);
                mma8(Sacc[1][nt], a[1], bf);
            }
        }

#pragma unroll
        for (int mt = 0; mt < 2; mt++) {
            int rl0 = wm * 32 + mt * 16 + gid;
            int rl1 = rl0 + 8;
            const int* mr0 = mask + ((size_t)b * SQ + q0 + rl0) * SQ + kb * 64 + wn * 32;
            const int* mr1 = mask + ((size_t)b * SQ + q0 + rl1) * SQ + kb * 64 + wn * 32;
            float* sr0 = sc + ((size_t)hb * SQ + q0 + rl0) * SQ + kb * 64 + wn * 32;
            float* sr1 = sc + ((size_t)hb * SQ + q0 + rl1) * SQ + kb * 64 + wn * 32;
#pragma unroll
            for (int nt = 0; nt < 4; nt++) {
                int cl = nt * 8 + 2 * tig;
                int2 m0 = *(const int2*)(mr0 + cl);
                int2 m1 = *(const int2*)(mr1 + cl);
                float s00 = m0.x ? Sacc[mt][nt][0] * 0.125f : NEGINF;
                float s01 = m0.y ? Sacc[mt][nt][1] * 0.125f : NEGINF;
                float s10 = m1.x ? Sacc[mt][nt][2] * 0.125f : NEGINF;
                float s11 = m1.y ? Sacc[mt][nt][3] * 0.125f : NEGINF;
                *(float2*)(sr0 + cl) = make_float2(s00, s01);
                *(float2*)(sr1 + cl) = make_float2(s10, s11);
                float e00 = __expf(s00), e01 = __expf(s01);
                float e10 = __expf(s10), e11 = __expf(s11);
                rs[mt][0] += e00 + e01;
                rs[mt][1] += e10 + e11;
                int pc = wn * 32 + cl;
                *(float2*)&Ps[rl0 * 68 + pc] = make_float2(f2tf(e00), f2tf(e01));
                *(float2*)&Ps[rl1 * 68 + pc] = make_float2(f2tf(e10), f2tf(e11));
            }
        }
        __syncthreads();

#pragma unroll
        for (int ks = 0; ks < 8; ks++) {
            int k0 = ks * 8;
            float a[2][4];
#pragma unroll
            for (int mt = 0; mt < 2; mt++) {
                int m = wm * 32 + mt * 16 + gid;
                a[mt][0] = Ps[m * 68 + k0 + tig];
                a[mt][1] = Ps[(m + 8) * 68 + k0 + tig];
                a[mt][2] = Ps[m * 68 + k0 + tig + 4];
                a[mt][3] = Ps[(m + 8) * 68 + k0 + tig + 4];
            }
#pragma unroll
            for (int nt = 0; nt < 4; nt++) {
                int n = wn * 32 + nt * 8 + gid;
                float bf[2];
                bf[0] = Vp[(k0 + tig) * 68 + n];
                bf[1] = Vp[(k0 + tig + 4) * 68 + n];
                mma8(Oacc[0][nt], a[0], bf);
                mma8(Oacc[1][nt], a[1], bf);
            }
        }
    }

#pragma unroll
    for (int mt = 0; mt < 2; mt++)
#pragma unroll
        for (int hh = 0; hh < 2; hh++) {
            float v = rs[mt][hh];
            v += __shfl_xor_sync(0xffffffffu, v, 1);
            v += __shfl_xor_sync(0xffffffffu, v, 2);
            if (tig == 0) atomicAdd(&rsum[wm * 32 + mt * 16 + hh * 8 + gid], v);
        }
    __syncthreads();

#pragma unroll
    for (int mt = 0; mt < 2; mt++) {
        int rl0 = wm * 32 + mt * 16 + gid;
        int rl1 = rl0 + 8;
        float inv0 = 1.0f / rsum[rl0];
        float inv1 = 1.0f / rsum[rl1];
        float* c0 = g_concat + ((size_t)b * SQ + q0 + rl0) * DM + h * DK + wn * 32;
        float* c1 = g_concat + ((size_t)b * SQ + q0 + rl1) * DM + h * DK + wn * 32;
#pragma unroll
        for (int nt = 0; nt < 4; nt++) {
            int cl = nt * 8 + 2 * tig;
            *(float2*)(c0 + cl) = make_float2(f2tf(Oacc[mt][nt][0] * inv0), f2tf(Oacc[mt][nt][1] * inv0));
            *(float2*)(c1 + cl) = make_float2(f2tf(Oacc[mt][nt][2] * inv1), f2tf(Oacc[mt][nt][3] * inv1));
        }
    }
}

// ---------------------------------------------------------------------------
// Kernel 3: out = concat @ Wo. BK=32, 3-stage, no in-loop cvts
// (g_concat and g_wo pre-rounded). fp32 output stores.
// ---------------------------------------------------------------------------
__global__ __launch_bounds__(256) void outproj_mma(float* __restrict__ out)
{
    const int row0 = blockIdx.x * 128;
    const int col0 = blockIdx.y * 128;

    extern __shared__ __align__(16) float sh[];
    float* As = sh;
    float* Bs = sh + 3 * 128 * 36;
    const uint32_t sA = (uint32_t)__cvta_generic_to_shared(As);
    const uint32_t sB = (uint32_t)__cvta_generic_to_shared(Bs);
    const uint32_t ASZ = 128 * 36 * 4, BSZ = 32 * 136 * 4;

    const int t    = threadIdx.x;
    const int warp = t >> 5, lane = t & 31;
    const int gid  = lane >> 2, tig = lane & 3;
    const int mb   = (warp >> 1) * 32;
    const int nb   = (warp & 1) * 64;

    const float* aptr[4]; uint32_t aoff[4];
    const float* bptr[4]; uint32_t boff[4];
#pragma unroll
    for (int u = 0; u < 4; u++) {
        int c = t + u * 256;
        int arow = c >> 3, k4 = c & 7;
        aptr[u] = g_concat + (size_t)(row0 + arow) * DM + k4 * 4;
        aoff[u] = (arow * 36 + k4 * 4) * 4;
        int brow = c >> 5, c4 = c & 31;
        bptr[u] = g_wo + (size_t)brow * DM + col0 + c4 * 4;
        boff[u] = (brow * 136 + c4 * 4) * 4;
    }

    float acc[2][8][4] = {};
    const int NT = 32;

#pragma unroll
    for (int p = 0; p < 2; p++) {
#pragma unroll
        for (int u = 0; u < 4; u++) {
            cp16(sA + p * ASZ + aoff[u], aptr[u] + p * 32);
            cp16(sB + p * BSZ + boff[u], bptr[u] + (size_t)(p * 32) * DM);
        }
        cp_commit();
    }

    int slot = 0;
    for (int tt = 0; tt < NT; tt++) {
        cp_wait1();
        __syncthreads();
        if (tt + 2 < NT) {
            const int ps = (tt + 2) % 3;
            const int kt = (tt + 2) * 32;
#pragma unroll
            for (int u = 0; u < 4; u++) {
                cp16(sA + ps * ASZ + aoff[u], aptr[u] + kt);
                cp16(sB + ps * BSZ + boff[u], bptr[u] + (size_t)kt * DM);
            }
        }
        cp_commit();

        const float* Ap = As + slot * 128 * 36;
        const float* Bp = Bs + slot * 32 * 136;
#pragma unroll
        for (int ks = 0; ks < 32; ks += 8) {
            float a[2][4], bf[8][2];
#pragma unroll
            for (int mt = 0; mt < 2; mt++) {
                int m = mb + mt * 16 + gid;
                a[mt][0] = Ap[m * 36 + ks + tig];
                a[mt][1] = Ap[(m + 8) * 36 + ks + tig];
                a[mt][2] = Ap[m * 36 + ks + tig + 4];
                a[mt][3] = Ap[(m + 8) * 36 + ks + tig + 4];
            }
#pragma unroll
            for (int nt = 0; nt < 8; nt++) {
                int n = nb + nt * 8 + gid;
                bf[nt][0] = Bp[(ks + tig) * 136 + n];
                bf[nt][1] = Bp[(ks + tig + 4) * 136 + n];
            }
#pragma unroll
            for (int mt = 0; mt < 2; mt++)
#pragma unroll
                for (int nt = 0; nt < 8; nt++) mma8(acc[mt][nt], a[mt], bf[nt]);
        }
        slot = (slot + 1 == 3) ? 0 : slot + 1;
    }

#pragma unroll
    for (int mt = 0; mt < 2; mt++) {
        int r = row0 + mb + mt * 16 + gid;
#pragma unroll
        for (int nt = 0; nt < 8; nt++) {
            int col = col0 + nb + nt * 8 + 2 * tig;
            *(float2*)(out + (size_t)r * DM + col)       = make_float2(acc[mt][nt][0], acc[mt][nt][1]);
            *(float2*)(out + (size_t)(r + 8) * DM + col) = make_float2(acc[mt][nt][2], acc[mt][nt][3]);
        }
    }
}

// ---------------------------------------------------------------------------
extern "C" void kernel_launch(void* const* d_in, const int* in_sizes, int n_in,
                              void* d_out, int out_size)
{
    const float* q    = (const float*)d_in[0];
    const float* k    = (const float*)d_in[1];
    const float* v    = (const float*)d_in[2];
    const int*   mask = (const int*)  d_in[3];
    const float* Wq   = (const float*)d_in[4];
    const float* Wk   = (const float*)d_in[5];
    const float* Wv   = (const float*)d_in[6];
    const float* Wo   = (const float*)d_in[7];

    float* out = (float*)d_out;
    float* scp = out + (size_t)MR * DM;

    static int smem_set = 0;
    if (!smem_set) {
        cudaFuncSetAttribute(proj_mma,    cudaFuncAttributeMaxDynamicSharedMemorySize, 107520);
        cudaFuncSetAttribute(outproj_mma, cudaFuncAttributeMaxDynamicSharedMemorySize, 107520);
        cudaFuncSetAttribute(attn_mma,    cudaFuncAttributeMaxDynamicSharedMemorySize, 139776);
        smem_set = 1;
    }

    float *dxq, *dxk, *dxv, *dwq, *dwk, *dwv, *dwo;
    cudaGetSymbolAddress((void**)&dxq, g_xq);
    cudaGetSymbolAddress((void**)&dxk, g_xk);
    cudaGetSymbolAddress((void**)&dxv, g_xv);
    cudaGetSymbolAddress((void**)&dwq, g_wq);
    cudaGetSymbolAddress((void**)&dwk, g_wk);
    cudaGetSymbolAddress((void**)&dwv, g_wv);
    cudaGetSymbolAddress((void**)&dwo, g_wo);

    prep_round<<<MR * DM / 1024, 256>>>(q, dxq);
    prep_round<<<MR * DM / 1024, 256>>>(k, dxk);
    prep_round<<<MR * DM / 1024, 256>>>(v, dxv);
    prep_round<<<NH * DM * DK / 1024, 256>>>(Wq, dwq);
    prep_round<<<NH * DM * DK / 1024, 256>>>(Wk, dwk);
    prep_round<<<NH * DM * DK / 1024, 256>>>(Wv, dwv);
    prep_round<<<NH * DK * DM / 1024, 256>>>(Wo, dwo);

    proj_mma   <<<dim3(32, 8, 3), 256, 107520>>>();
    attn_mma   <<<dim3(8, 64), 256, 139776>>>(mask, scp);
    outproj_mma<<<dim3(32, 8), 256, 107520>>>(out);
}

// round 7
// speedup vs baseline: 4.7238x; 1.8879x over previous
#include <cuda_runtime.h>
#include <cuda_fp16.h>
#include <cstdint>

#define NH 16
#define NB 4
#define SQ 1024
#define DM 1024
#define DK 64
#define MR (NB * SQ)
#define HB (NH * NB)

// fp16 scratch (__device__ globals per allocation-free rule)
__device__ __half g_xq[(size_t)MR * DM];
__device__ __half g_xk[(size_t)MR * DM];
__device__ __half g_xv[(size_t)MR * DM];
__device__ __half g_wq[(size_t)NH * DM * DK];
__device__ __half g_wk[(size_t)NH * DM * DK];
__device__ __half g_wv[(size_t)NH * DM * DK];
__device__ __half g_wo[(size_t)DM * DM];
__device__ __half g_qh[(size_t)HB * SQ * DK];
__device__ __half g_kh[(size_t)HB * SQ * DK];
__device__ __half g_vh[(size_t)HB * SQ * DK];
__device__ __half g_ch[(size_t)MR * DM];

__device__ __forceinline__ uint32_t h2u(__half2 h) { return *(uint32_t*)&h; }

__device__ __forceinline__ void ldsm4(uint32_t* r, uint32_t addr) {
    asm volatile("ldmatrix.sync.aligned.m8n8.x4.shared.b16 {%0,%1,%2,%3}, [%4];"
        : "=r"(r[0]), "=r"(r[1]), "=r"(r[2]), "=r"(r[3]) : "r"(addr));
}
__device__ __forceinline__ void ldsm4t(uint32_t* r, uint32_t addr) {
    asm volatile("ldmatrix.sync.aligned.m8n8.x4.trans.shared.b16 {%0,%1,%2,%3}, [%4];"
        : "=r"(r[0]), "=r"(r[1]), "=r"(r[2]), "=r"(r[3]) : "r"(addr));
}
__device__ __forceinline__ void mma16(float* d, const uint32_t* a, const uint32_t* b) {
    asm volatile("mma.sync.aligned.m16n8k16.row.col.f32.f16.f16.f32 "
        "{%0,%1,%2,%3}, {%4,%5,%6,%7}, {%8,%9}, {%0,%1,%2,%3};"
        : "+f"(d[0]), "+f"(d[1]), "+f"(d[2]), "+f"(d[3])
        : "r"(a[0]), "r"(a[1]), "r"(a[2]), "r"(a[3]), "r"(b[0]), "r"(b[1]));
}
__device__ __forceinline__ void cp16(uint32_t dst, const void* src) {
    asm volatile("cp.async.cg.shared.global [%0], [%1], 16;" :: "r"(dst), "l"(src));
}
__device__ __forceinline__ void cp_commit() { asm volatile("cp.async.commit_group;"); }
__device__ __forceinline__ void cp_wait0() { asm volatile("cp.async.wait_group 0;"); }
__device__ __forceinline__ void cp_wait1() { asm volatile("cp.async.wait_group 1;"); }

// ---------------------------------------------------------------------------
// Kernel 0: fp32 -> fp16 conversion, 8 elems/thread.
// ---------------------------------------------------------------------------
__global__ __launch_bounds__(256) void prep_half(
    const float* __restrict__ src, __half* __restrict__ dst)
{
    size_t i = (size_t)blockIdx.x * 256 + threadIdx.x;
    float4 a = ((const float4*)src)[i * 2];
    float4 b = ((const float4*)src)[i * 2 + 1];
    uint4 o;
    o.x = h2u(__floats2half2_rn(a.x, a.y));
    o.y = h2u(__floats2half2_rn(a.z, a.w));
    o.z = h2u(__floats2half2_rn(b.x, b.y));
    o.w = h2u(__floats2half2_rn(b.z, b.w));
    ((uint4*)dst)[i] = o;
}

// ---------------------------------------------------------------------------
// Kernel 1: per-head projections. fp16 mma m16n8k16, ldmatrix, BK=32,
// 3-stage cp.async. A smem [128 m][40 k], B smem [32 k][136 n].
// ---------------------------------------------------------------------------
__global__ __launch_bounds__(256) void proj_mma()
{
    const int which = blockIdx.z;
    const __half* X = (which == 0) ? g_xq : (which == 1) ? g_xk : g_xv;
    const __half* W = (which == 0) ? g_wq : (which == 1) ? g_wk : g_wv;
    __half* O       = (which == 0) ? g_qh : (which == 1) ? g_kh : g_vh;
    const int row0 = blockIdx.x * 128;
    const int col0 = blockIdx.y * 128;

    extern __shared__ __align__(16) __half sh[];
    __half* As = sh;                  // [3][128*40]
    __half* Bs = sh + 3 * 128 * 40;   // [3][32*136]
    const uint32_t sA = (uint32_t)__cvta_generic_to_shared(As);
    const uint32_t sB = (uint32_t)__cvta_generic_to_shared(Bs);
    const uint32_t ASZ = 128 * 40 * 2, BSZ = 32 * 136 * 2;

    const int t    = threadIdx.x;
    const int warp = t >> 5, lane = t & 31;
    const int gid  = lane >> 2, tig = lane & 3;
    const int mb   = (warp >> 1) * 32;
    const int nb   = (warp & 1) * 64;
    const int lr   = lane & 15;
    const int lc   = (lane >> 4) * 8;

    // ldmatrix per-thread base offsets (bytes)
    uint32_t aoffm[2], boffn[4];
#pragma unroll
    for (int mt = 0; mt < 2; mt++) aoffm[mt] = ((mb + mt * 16 + lr) * 40 + lc) * 2;
#pragma unroll
    for (int p = 0; p < 4; p++) boffn[p] = (lr * 136 + nb + p * 16 + lc) * 2;

    // cp.async setup: A 2/thread, B 2/thread
    const __half* aptr[2]; uint32_t aoff[2];
    const __half* bptr[2]; uint32_t boff[2];
#pragma unroll
    for (int u = 0; u < 2; u++) {
        int c = t + u * 256;
        int arow = c >> 2, aseg = c & 3;             // 128 rows x 4 segs(8h)
        aptr[u] = X + (size_t)(row0 + arow) * DM + aseg * 8;
        aoff[u] = (arow * 40 + aseg * 8) * 2;
        int brow = c >> 4, bseg = c & 15;            // 32 rows x 16 segs
        int colh = col0 + bseg * 8, hh = colh >> 6, kk = colh & 63;
        bptr[u] = W + (size_t)hh * DM * DK + (size_t)brow * DK + kk;
        boff[u] = (brow * 136 + bseg * 8) * 2;
    }

    float acc[2][8][4] = {};
    const int NT = 32;

#pragma unroll
    for (int p = 0; p < 2; p++) {
#pragma unroll
        for (int u = 0; u < 2; u++) {
            cp16(sA + p * ASZ + aoff[u], aptr[u] + p * 32);
            cp16(sB + p * BSZ + boff[u], bptr[u] + (size_t)(p * 32) * DK);
        }
        cp_commit();
    }

    int slot = 0;
    for (int tt = 0; tt < NT; tt++) {
        cp_wait1();
        __syncthreads();
        if (tt + 2 < NT) {
            const int ps = (tt + 2) % 3;
            const int kt = (tt + 2) * 32;
#pragma unroll
            for (int u = 0; u < 2; u++) {
                cp16(sA + ps * ASZ + aoff[u], aptr[u] + kt);
                cp16(sB + ps * BSZ + boff[u], bptr[u] + (size_t)kt * DK);
            }
        }
        cp_commit();

        const uint32_t sAs = sA + slot * ASZ;
        const uint32_t sBs = sB + slot * BSZ;
#pragma unroll
        for (int ks = 0; ks < 32; ks += 16) {
            uint32_t a[2][4], b[8][2];
#pragma unroll
            for (int mt = 0; mt < 2; mt++) ldsm4(a[mt], sAs + aoffm[mt] + ks * 2);
#pragma unroll
            for (int p = 0; p < 4; p++) {
                uint32_t r[4];
                ldsm4t(r, sBs + boffn[p] + ks * 136 * 2);
                b[p * 2][0] = r[0]; b[p * 2][1] = r[1];
                b[p * 2 + 1][0] = r[2]; b[p * 2 + 1][1] = r[3];
            }
#pragma unroll
            for (int mt = 0; mt < 2; mt++)
#pragma unroll
                for (int nt = 0; nt < 8; nt++) mma16(acc[mt][nt], a[mt], b[nt]);
        }
        slot = (slot + 1 == 3) ? 0 : slot + 1;
    }

#pragma unroll
    for (int mt = 0; mt < 2; mt++) {
        int r0 = row0 + mb + mt * 16 + gid;
        int bb = r0 >> 10, s0 = r0 & 1023;
#pragma unroll
        for (int nt = 0; nt < 8; nt++) {
            int col = col0 + nb + nt * 8 + 2 * tig;
            int hh = col >> 6, kk = col & 63;
            __half* base = O + (size_t)(hh * NB + bb) * SQ * DK;
            *(__half2*)(base + (size_t)s0 * DK + kk) =
                __floats2half2_rn(acc[mt][nt][0], acc[mt][nt][1]);
            *(__half2*)(base + (size_t)(s0 + 8) * DK + kk) =
                __floats2half2_rn(acc[mt][nt][2], acc[mt][nt][3]);
        }
    }
}

// ---------------------------------------------------------------------------
// Kernel 2: fused attention, fp16 mma + ldmatrix. CTA = (hb, 128 q),
// 16 key tiles of 64, K/V double-buffered. Warp grid 4x2.
// ---------------------------------------------------------------------------
__global__ __launch_bounds__(256) void attn_mma(
    const int* __restrict__ mask, float* __restrict__ sc)
{
    extern __shared__ __align__(16) __half smh[];
    __half* Qs  = smh;                    // [128][72]
    __half* Ps  = Qs + 128 * 72;          // [128][72]
    __half* Ksm = Ps + 128 * 72;          // [2][64][72]
    __half* Vsm = Ksm + 2 * 64 * 72;      // [2][64][72]
    float* rsum = (float*)(Vsm + 2 * 64 * 72);  // [128]

    const uint32_t qsm = (uint32_t)__cvta_generic_to_shared(Qs);
    const uint32_t psm = (uint32_t)__cvta_generic_to_shared(Ps);
    const uint32_t ksm = (uint32_t)__cvta_generic_to_shared(Ksm);
    const uint32_t vsm = (uint32_t)__cvta_generic_to_shared(Vsm);
    const uint32_t TSZ = 64 * 72 * 2;

    const int hb = blockIdx.y;
    const int h  = hb >> 2, b = hb & 3;
    const int q0 = blockIdx.x * 128;
    const int t = threadIdx.x, warp = t >> 5, lane = t & 31;
    const int gid = lane >> 2, tig = lane & 3;
    const int wm = warp >> 1, wn = warp & 1;
    const int lr = lane & 15;
    const int lc = (lane >> 4) * 8;

    const __half* qbase = g_qh + ((size_t)hb * SQ + q0) * DK;
    const __half* kbase = g_kh + (size_t)hb * SQ * DK;
    const __half* vbase = g_vh + (size_t)hb * SQ * DK;

    // ldmatrix per-thread base offsets (bytes)
    uint32_t qoffm[2], poffm[2], koffn[2], voffn[2];
#pragma unroll
    for (int mt = 0; mt < 2; mt++) {
        qoffm[mt] = ((wm * 32 + mt * 16 + lr) * 72 + lc) * 2;
        poffm[mt] = qoffm[mt];
    }
#pragma unroll
    for (int p = 0; p < 2; p++) {
        koffn[p] = ((wn * 32 + p * 16 + ((lane >> 4) & 1) * 8 + (lane & 7)) * 72
                    + ((lane >> 3) & 1) * 8) * 2;
        voffn[p] = (lr * 72 + wn * 32 + p * 16 + lc) * 2;
    }

    if (t < 128) rsum[t] = 0.f;

    // prologue: Q (4/thread) + K0/V0 (2+2/thread)
#pragma unroll
    for (int u = 0; u < 4; u++) {
        int c = t + u * 256;
        int row = c >> 3, seg = c & 7;
        cp16(qsm + (row * 72 + seg * 8) * 2, qbase + (size_t)row * DK + seg * 8);
    }
#pragma unroll
    for (int u = 0; u < 2; u++) {
        int c = t + u * 256;
        int row = c >> 3, seg = c & 7;
        cp16(ksm + (row * 72 + seg * 8) * 2, kbase + (size_t)row * DK + seg * 8);
        cp16(vsm + (row * 72 + seg * 8) * 2, vbase + (size_t)row * DK + seg * 8);
    }
    cp_commit();

    float Oacc[2][4][4] = {};
    float rs[2][2] = {};
    const float NEGINF = __int_as_float(0xff800000u);

    for (int kb = 0; kb < 16; kb++) {
        const int slot = kb & 1;
        cp_wait0();
        __syncthreads();
        if (kb + 1 < 16) {
            const int so = slot ^ 1;
            const __half* kp = kbase + (size_t)(kb + 1) * 64 * DK;
            const __half* vp = vbase + (size_t)(kb + 1) * 64 * DK;
#pragma unroll
            for (int u = 0; u < 2; u++) {
                int c = t + u * 256;
                int row = c >> 3, seg = c & 7;
                cp16(ksm + so * TSZ + (row * 72 + seg * 8) * 2, kp + (size_t)row * DK + seg * 8);
                cp16(vsm + so * TSZ + (row * 72 + seg * 8) * 2, vp + (size_t)row * DK + seg * 8);
            }
        }
        cp_commit();

        const uint32_t Kp = ksm + slot * TSZ;
        const uint32_t Vp = vsm + slot * TSZ;

        // S = Q @ K^T : warp 32q x 32key, d = 64 -> 4 k16 steps
        float Sacc[2][4][4] = {};
#pragma unroll
        for (int ks = 0; ks < 4; ks++) {
            const int k0 = ks * 16;
            uint32_t a[2][4], bk[4][2];
#pragma unroll
            for (int mt = 0; mt < 2; mt++) ldsm4(a[mt], qsm + qoffm[mt] + k0 * 2);
#pragma unroll
            for (int p = 0; p < 2; p++) {
                uint32_t r[4];
                ldsm4(r, Kp + koffn[p] + k0 * 2);
                bk[p * 2][0] = r[0]; bk[p * 2][1] = r[1];
                bk[p * 2 + 1][0] = r[2]; bk[p * 2 + 1][1] = r[3];
            }
#pragma unroll
            for (int mt = 0; mt < 2; mt++)
#pragma unroll
                for (int nt = 0; nt < 4; nt++) mma16(Sacc[mt][nt], a[mt], bk[nt]);
        }

        // scale, mask, write scores (fp32), exp -> Ps (fp16) + row sums
#pragma unroll
        for (int mt = 0; mt < 2; mt++) {
            int rl0 = wm * 32 + mt * 16 + gid;
            int rl1 = rl0 + 8;
            const int* mr0 = mask + ((size_t)b * SQ + q0 + rl0) * SQ + kb * 64 + wn * 32;
            const int* mr1 = mask + ((size_t)b * SQ + q0 + rl1) * SQ + kb * 64 + wn * 32;
            float* sr0 = sc + ((size_t)hb * SQ + q0 + rl0) * SQ + kb * 64 + wn * 32;
            float* sr1 = sc + ((size_t)hb * SQ + q0 + rl1) * SQ + kb * 64 + wn * 32;
#pragma unroll
            for (int nt = 0; nt < 4; nt++) {
                int cl = nt * 8 + 2 * tig;
                int2 m0 = *(const int2*)(mr0 + cl);
                int2 m1 = *(const int2*)(mr1 + cl);
                float s00 = m0.x ? Sacc[mt][nt][0] * 0.125f : NEGINF;
                float s01 = m0.y ? Sacc[mt][nt][1] * 0.125f : NEGINF;
                float s10 = m1.x ? Sacc[mt][nt][2] * 0.125f : NEGINF;
                float s11 = m1.y ? Sacc[mt][nt][3] * 0.125f : NEGINF;
                *(float2*)(sr0 + cl) = make_float2(s00, s01);
                *(float2*)(sr1 + cl) = make_float2(s10, s11);
                float e00 = __expf(s00), e01 = __expf(s01);
                float e10 = __expf(s10), e11 = __expf(s11);
                rs[mt][0] += e00 + e01;
                rs[mt][1] += e10 + e11;
                int pc = wn * 32 + cl;
                *(__half2*)&Ps[rl0 * 72 + pc] = __floats2half2_rn(e00, e01);
                *(__half2*)&Ps[rl1 * 72 + pc] = __floats2half2_rn(e10, e11);
            }
        }
        __syncthreads();

        // O += P @ V : warp 32q x 32d, k = 64 keys -> 4 k16 steps
#pragma unroll
        for (int ks = 0; ks < 4; ks++) {
            const int k0 = ks * 16;
            uint32_t a[2][4], bv[4][2];
#pragma unroll
            for (int mt = 0; mt < 2; mt++) ldsm4(a[mt], psm + poffm[mt] + k0 * 2);
#pragma unroll
            for (int p = 0; p < 2; p++) {
                uint32_t r[4];
                ldsm4t(r, Vp + voffn[p] + k0 * 72 * 2);
                bv[p * 2][0] = r[0]; bv[p * 2][1] = r[1];
                bv[p * 2 + 1][0] = r[2]; bv[p * 2 + 1][1] = r[3];
            }
#pragma unroll
            for (int mt = 0; mt < 2; mt++)
#pragma unroll
                for (int nt = 0; nt < 4; nt++) mma16(Oacc[mt][nt], a[mt], bv[nt]);
        }
    }

    // reduce row sums across quad lanes + the two wn warps
#pragma unroll
    for (int mt = 0; mt < 2; mt++)
#pragma unroll
        for (int hh = 0; hh < 2; hh++) {
            float v = rs[mt][hh];
            v += __shfl_xor_sync(0xffffffffu, v, 1);
            v += __shfl_xor_sync(0xffffffffu, v, 2);
            if (tig == 0) atomicAdd(&rsum[wm * 32 + mt * 16 + hh * 8 + gid], v);
        }
    __syncthreads();

#pragma unroll
    for (int mt = 0; mt < 2; mt++) {
        int rl0 = wm * 32 + mt * 16 + gid;
        int rl1 = rl0 + 8;
        float inv0 = 1.0f / rsum[rl0];
        float inv1 = 1.0f / rsum[rl1];
        __half* c0 = g_ch + ((size_t)b * SQ + q0 + rl0) * DM + h * DK + wn * 32;
        __half* c1 = g_ch + ((size_t)b * SQ + q0 + rl1) * DM + h * DK + wn * 32;
#pragma unroll
        for (int nt = 0; nt < 4; nt++) {
            int cl = nt * 8 + 2 * tig;
            *(__half2*)(c0 + cl) = __floats2half2_rn(Oacc[mt][nt][0] * inv0, Oacc[mt][nt][1] * inv0);
            *(__half2*)(c1 + cl) = __floats2half2_rn(Oacc[mt][nt][2] * inv1, Oacc[mt][nt][3] * inv1);
        }
    }
}

// ---------------------------------------------------------------------------
// Kernel 3: out = concat @ Wo, fp16 mma + ldmatrix, BK=32, 3-stage. fp32 out.
// ---------------------------------------------------------------------------
__global__ __launch_bounds__(256) void outproj_mma(float* __restrict__ out)
{
    const int row0 = blockIdx.x * 128;
    const int col0 = blockIdx.y * 128;

    extern __shared__ __align__(16) __half sh[];
    __half* As = sh;
    __half* Bs = sh + 3 * 128 * 40;
    const uint32_t sA = (uint32_t)__cvta_generic_to_shared(As);
    const uint32_t sB = (uint32_t)__cvta_generic_to_shared(Bs);
    const uint32_t ASZ = 128 * 40 * 2, BSZ = 32 * 136 * 2;

    const int t    = threadIdx.x;
    const int warp = t >> 5, lane = t & 31;
    const int gid  = lane >> 2, tig = lane & 3;
    const int mb   = (warp >> 1) * 32;
    const int nb   = (warp & 1) * 64;
    const int lr   = lane & 15;
    const int lc   = (lane >> 4) * 8;

    uint32_t aoffm[2], boffn[4];
#pragma unroll
    for (int mt = 0; mt < 2; mt++) aoffm[mt] = ((mb + mt * 16 + lr) * 40 + lc) * 2;
#pragma unroll
    for (int p = 0; p < 4; p++) boffn[p] = (lr * 136 + nb + p * 16 + lc) * 2;

    const __half* aptr[2]; uint32_t aoff[2];
    const __half* bptr[2]; uint32_t boff[2];
#pragma unroll
    for (int u = 0; u < 2; u++) {
        int c = t + u * 256;
        int arow = c >> 2, aseg = c & 3;
        aptr[u] = g_ch + (size_t)(row0 + arow) * DM + aseg * 8;
        aoff[u] = (arow * 40 + aseg * 8) * 2;
        int brow = c >> 4, bseg = c & 15;
        bptr[u] = g_wo + (size_t)brow * DM + col0 + bseg * 8;
        boff[u] = (brow * 136 + bseg * 8) * 2;
    }

    float acc[2][8][4] = {};
    const int NT = 32;

#pragma unroll
    for (int p = 0; p < 2; p++) {
#pragma unroll
        for (int u = 0; u < 2; u++) {
            cp16(sA + p * ASZ + aoff[u], aptr[u] + p * 32);
            cp16(sB + p * BSZ + boff[u], bptr[u] + (size_t)(p * 32) * DM);
        }
        cp_commit();
    }

    int slot = 0;
    for (int tt = 0; tt < NT; tt++) {
        cp_wait1();
        __syncthreads();
        if (tt + 2 < NT) {
            const int ps = (tt + 2) % 3;
            const int kt = (tt + 2) * 32;
#pragma unroll
            for (int u = 0; u < 2; u++) {
                cp16(sA + ps * ASZ + aoff[u], aptr[u] + kt);
                cp16(sB + ps * BSZ + boff[u], bptr[u] + (size_t)kt * DM);
            }
        }
        cp_commit();

        const uint32_t sAs = sA + slot * ASZ;
        const uint32_t sBs = sB + slot * BSZ;
#pragma unroll
        for (int ks = 0; ks < 32; ks += 16) {
            uint32_t a[2][4], b[8][2];
#pragma unroll
            for (int mt = 0; mt < 2; mt++) ldsm4(a[mt], sAs + aoffm[mt] + ks * 2);
#pragma unroll
            for (int p = 0; p < 4; p++) {
                uint32_t r[4];
                ldsm4t(r, sBs + boffn[p] + ks * 136 * 2);
                b[p * 2][0] = r[0]; b[p * 2][1] = r[1];
                b[p * 2 + 1][0] = r[2]; b[p * 2 + 1][1] = r[3];
            }
#pragma unroll
            for (int mt = 0; mt < 2; mt++)
#pragma unroll
                for (int nt = 0; nt < 8; nt++) mma16(acc[mt][nt], a[mt], b[nt]);
        }
        slot = (slot + 1 == 3) ? 0 : slot + 1;
    }

#pragma unroll
    for (int mt = 0; mt < 2; mt++) {
        int r = row0 + mb + mt * 16 + gid;
#pragma unroll
        for (int nt = 0; nt < 8; nt++) {
            int col = col0 + nb + nt * 8 + 2 * tig;
            *(float2*)(out + (size_t)r * DM + col)       = make_float2(acc[mt][nt][0], acc[mt][nt][1]);
            *(float2*)(out + (size_t)(r + 8) * DM + col) = make_float2(acc[mt][nt][2], acc[mt][nt][3]);
        }
    }
}

// ---------------------------------------------------------------------------
extern "C" void kernel_launch(void* const* d_in, const int* in_sizes, int n_in,
                              void* d_out, int out_size)
{
    const float* q    = (const float*)d_in[0];
    const float* k    = (const float*)d_in[1];
    const float* v    = (const float*)d_in[2];
    const int*   mask = (const int*)  d_in[3];
    const float* Wq   = (const float*)d_in[4];
    const float* Wk   = (const float*)d_in[5];
    const float* Wv   = (const float*)d_in[6];
    const float* Wo   = (const float*)d_in[7];

    float* out = (float*)d_out;
    float* scp = out + (size_t)MR * DM;

    static int smem_set = 0;
    if (!smem_set) {
        cudaFuncSetAttribute(proj_mma,    cudaFuncAttributeMaxDynamicSharedMemorySize, 56832);
        cudaFuncSetAttribute(outproj_mma, cudaFuncAttributeMaxDynamicSharedMemorySize, 56832);
        cudaFuncSetAttribute(attn_mma,    cudaFuncAttributeMaxDynamicSharedMemorySize, 111104);
        smem_set = 1;
    }

    __half *dxq, *dxk, *dxv, *dwq, *dwk, *dwv, *dwo;
    cudaGetSymbolAddress((void**)&dxq, g_xq);
    cudaGetSymbolAddress((void**)&dxk, g_xk);
    cudaGetSymbolAddress((void**)&dxv, g_xv);
    cudaGetSymbolAddress((void**)&dwq, g_wq);
    cudaGetSymbolAddress((void**)&dwk, g_wk);
    cudaGetSymbolAddress((void**)&dwv, g_wv);
    cudaGetSymbolAddress((void**)&dwo, g_wo);

    prep_half<<<MR * DM / 2048, 256>>>(q, dxq);
    prep_half<<<MR * DM / 2048, 256>>>(k, dxk);
    prep_half<<<MR * DM / 2048, 256>>>(v, dxv);
    prep_half<<<NH * DM * DK / 2048, 256>>>(Wq, dwq);
    prep_half<<<NH * DM * DK / 2048, 256>>>(Wk, dwk);
    prep_half<<<NH * DM * DK / 2048, 256>>>(Wv, dwv);
    prep_half<<<DM * DM / 2048, 256>>>(Wo, dwo);

    proj_mma   <<<dim3(32, 8, 3), 256, 56832>>>();
    attn_mma   <<<dim3(8, 64), 256, 111104>>>(mask, scp);
    outproj_mma<<<dim3(32, 8), 256, 56832>>>(out);
}

// round 8
// speedup vs baseline: 4.9680x; 1.0517x over previous
#include <cuda_runtime.h>
#include <cuda_fp16.h>
#include <cstdint>

#define NH 16
#define NB 4
#define SQ 1024
#define DM 1024
#define DK 64
#define MR (NB * SQ)
#define HB (NH * NB)

// fp16 scratch (__device__ globals per allocation-free rule)
__device__ __half g_xq[(size_t)MR * DM];
__device__ __half g_xk[(size_t)MR * DM];
__device__ __half g_xv[(size_t)MR * DM];
__device__ __half g_wq[(size_t)NH * DM * DK];
__device__ __half g_wk[(size_t)NH * DM * DK];
__device__ __half g_wv[(size_t)NH * DM * DK];
__device__ __half g_wo[(size_t)DM * DM];
__device__ __half g_qh[(size_t)HB * SQ * DK];
__device__ __half g_kh[(size_t)HB * SQ * DK];
__device__ __half g_vh[(size_t)HB * SQ * DK];
__device__ __half g_ch[(size_t)MR * DM];

__device__ __forceinline__ uint32_t h2u(__half2 h) { return *(uint32_t*)&h; }

__device__ __forceinline__ void ldsm4(uint32_t* r, uint32_t addr) {
    asm volatile("ldmatrix.sync.aligned.m8n8.x4.shared.b16 {%0,%1,%2,%3}, [%4];"
        : "=r"(r[0]), "=r"(r[1]), "=r"(r[2]), "=r"(r[3]) : "r"(addr));
}
__device__ __forceinline__ void ldsm4t(uint32_t* r, uint32_t addr) {
    asm volatile("ldmatrix.sync.aligned.m8n8.x4.trans.shared.b16 {%0,%1,%2,%3}, [%4];"
        : "=r"(r[0]), "=r"(r[1]), "=r"(r[2]), "=r"(r[3]) : "r"(addr));
}
__device__ __forceinline__ void mma16(float* d, const uint32_t* a, const uint32_t* b) {
    asm volatile("mma.sync.aligned.m16n8k16.row.col.f32.f16.f16.f32 "
        "{%0,%1,%2,%3}, {%4,%5,%6,%7}, {%8,%9}, {%0,%1,%2,%3};"
        : "+f"(d[0]), "+f"(d[1]), "+f"(d[2]), "+f"(d[3])
        : "r"(a[0]), "r"(a[1]), "r"(a[2]), "r"(a[3]), "r"(b[0]), "r"(b[1]));
}
__device__ __forceinline__ void cp16(uint32_t dst, const void* src) {
    asm volatile("cp.async.cg.shared.global [%0], [%1], 16;" :: "r"(dst), "l"(src));
}
__device__ __forceinline__ void cp_commit() { asm volatile("cp.async.commit_group;"); }
__device__ __forceinline__ void cp_wait0() { asm volatile("cp.async.wait_group 0;"); }
__device__ __forceinline__ void cp_wait1() { asm volatile("cp.async.wait_group 1;"); }

// ---------------------------------------------------------------------------
// Kernel 0: single fused fp32->fp16 conversion for all 7 input tensors.
// X blocks: 3 x 2048 (4M elems each), W blocks: 4 x 512 (1M elems each).
// ---------------------------------------------------------------------------
__global__ __launch_bounds__(256) void prep_all(
    const float* __restrict__ q, const float* __restrict__ k, const float* __restrict__ v,
    const float* __restrict__ wq, const float* __restrict__ wk, const float* __restrict__ wv,
    const float* __restrict__ wo)
{
    const int bb = blockIdx.x;
    const float* src; __half* dst; int inner;
    if (bb < 6144) {
        int which = bb >> 11;
        src = (which == 0) ? q : (which == 1) ? k : v;
        dst = (which == 0) ? g_xq : (which == 1) ? g_xk : g_xv;
        inner = bb & 2047;
    } else {
        int which = (bb - 6144) >> 9;
        src = (which == 0) ? wq : (which == 1) ? wk : (which == 2) ? wv : wo;
        dst = (which == 0) ? g_wq : (which == 1) ? g_wk : (which == 2) ? g_wv : g_wo;
        inner = (bb - 6144) & 511;
    }
    size_t i = (size_t)inner * 256 + threadIdx.x;   // uint4 index (8 halves)
    float4 a = ((const float4*)src)[i * 2];
    float4 b = ((const float4*)src)[i * 2 + 1];
    uint4 o;
    o.x = h2u(__floats2half2_rn(a.x, a.y));
    o.y = h2u(__floats2half2_rn(a.z, a.w));
    o.z = h2u(__floats2half2_rn(b.x, b.y));
    o.w = h2u(__floats2half2_rn(b.z, b.w));
    ((uint4*)dst)[i] = o;
}

// ---------------------------------------------------------------------------
// Kernel 1: per-head projections. fp16 mma m16n8k16, ldmatrix, BK=32,
// 3-stage cp.async. (unchanged from R7)
// ---------------------------------------------------------------------------
__global__ __launch_bounds__(256) void proj_mma()
{
    const int which = blockIdx.z;
    const __half* X = (which == 0) ? g_xq : (which == 1) ? g_xk : g_xv;
    const __half* W = (which == 0) ? g_wq : (which == 1) ? g_wk : g_wv;
    __half* O       = (which == 0) ? g_qh : (which == 1) ? g_kh : g_vh;
    const int row0 = blockIdx.x * 128;
    const int col0 = blockIdx.y * 128;

    extern __shared__ __align__(16) __half sh[];
    __half* As = sh;                  // [3][128*40]
    __half* Bs = sh + 3 * 128 * 40;   // [3][32*136]
    const uint32_t sA = (uint32_t)__cvta_generic_to_shared(As);
    const uint32_t sB = (uint32_t)__cvta_generic_to_shared(Bs);
    const uint32_t ASZ = 128 * 40 * 2, BSZ = 32 * 136 * 2;

    const int t    = threadIdx.x;
    const int warp = t >> 5, lane = t & 31;
    const int gid  = lane >> 2, tig = lane & 3;
    const int mb   = (warp >> 1) * 32;
    const int nb   = (warp & 1) * 64;
    const int lr   = lane & 15;
    const int lc   = (lane >> 4) * 8;

    uint32_t aoffm[2], boffn[4];
#pragma unroll
    for (int mt = 0; mt < 2; mt++) aoffm[mt] = ((mb + mt * 16 + lr) * 40 + lc) * 2;
#pragma unroll
    for (int p = 0; p < 4; p++) boffn[p] = (lr * 136 + nb + p * 16 + lc) * 2;

    const __half* aptr[2]; uint32_t aoff[2];
    const __half* bptr[2]; uint32_t boff[2];
#pragma unroll
    for (int u = 0; u < 2; u++) {
        int c = t + u * 256;
        int arow = c >> 2, aseg = c & 3;
        aptr[u] = X + (size_t)(row0 + arow) * DM + aseg * 8;
        aoff[u] = (arow * 40 + aseg * 8) * 2;
        int brow = c >> 4, bseg = c & 15;
        int colh = col0 + bseg * 8, hh = colh >> 6, kk = colh & 63;
        bptr[u] = W + (size_t)hh * DM * DK + (size_t)brow * DK + kk;
        boff[u] = (brow * 136 + bseg * 8) * 2;
    }

    float acc[2][8][4] = {};
    const int NT = 32;

#pragma unroll
    for (int p = 0; p < 2; p++) {
#pragma unroll
        for (int u = 0; u < 2; u++) {
            cp16(sA + p * ASZ + aoff[u], aptr[u] + p * 32);
            cp16(sB + p * BSZ + boff[u], bptr[u] + (size_t)(p * 32) * DK);
        }
        cp_commit();
    }

    int slot = 0;
    for (int tt = 0; tt < NT; tt++) {
        cp_wait1();
        __syncthreads();
        if (tt + 2 < NT) {
            const int ps = (tt + 2) % 3;
            const int kt = (tt + 2) * 32;
#pragma unroll
            for (int u = 0; u < 2; u++) {
                cp16(sA + ps * ASZ + aoff[u], aptr[u] + kt);
                cp16(sB + ps * BSZ + boff[u], bptr[u] + (size_t)kt * DK);
            }
        }
        cp_commit();

        const uint32_t sAs = sA + slot * ASZ;
        const uint32_t sBs = sB + slot * BSZ;
#pragma unroll
        for (int ks = 0; ks < 32; ks += 16) {
            uint32_t a[2][4], b[8][2];
#pragma unroll
            for (int mt = 0; mt < 2; mt++) ldsm4(a[mt], sAs + aoffm[mt] + ks * 2);
#pragma unroll
            for (int p = 0; p < 4; p++) {
                uint32_t r[4];
                ldsm4t(r, sBs + boffn[p] + ks * 136 * 2);
                b[p * 2][0] = r[0]; b[p * 2][1] = r[1];
                b[p * 2 + 1][0] = r[2]; b[p * 2 + 1][1] = r[3];
            }
#pragma unroll
            for (int mt = 0; mt < 2; mt++)
#pragma unroll
                for (int nt = 0; nt < 8; nt++) mma16(acc[mt][nt], a[mt], b[nt]);
        }
        slot = (slot + 1 == 3) ? 0 : slot + 1;
    }

#pragma unroll
    for (int mt = 0; mt < 2; mt++) {
        int r0 = row0 + mb + mt * 16 + gid;
        int bb = r0 >> 10, s0 = r0 & 1023;
#pragma unroll
        for (int nt = 0; nt < 8; nt++) {
            int col = col0 + nb + nt * 8 + 2 * tig;
            int hh = col >> 6, kk = col & 63;
            __half* base = O + (size_t)(hh * NB + bb) * SQ * DK;
            *(__half2*)(base + (size_t)s0 * DK + kk) =
                __floats2half2_rn(acc[mt][nt][0], acc[mt][nt][1]);
            *(__half2*)(base + (size_t)(s0 + 8) * DK + kk) =
                __floats2half2_rn(acc[mt][nt][2], acc[mt][nt][3]);
        }
    }
}

// ---------------------------------------------------------------------------
// Kernel 2: fused attention, REGISTER-RESIDENT P.
// 8 warps x 16 q-rows each; every warp owns the full 64-key strip, so the
// QK^T C-fragment converts in-register into the PV A-fragment (no Ps smem,
// no mid-tile syncthreads, no shared rsum). Q fragments in registers.
// ---------------------------------------------------------------------------
__global__ __launch_bounds__(256, 2) void attn_mma(
    const int* __restrict__ mask, float* __restrict__ sc)
{
    extern __shared__ __align__(16) __half smh[];
    __half* Qs  = smh;                    // [128][72] (staging, read once)
    __half* Ksm = Qs + 128 * 72;          // [2][64][72]
    __half* Vsm = Ksm + 2 * 64 * 72;      // [2][64][72]

    const uint32_t qsm = (uint32_t)__cvta_generic_to_shared(Qs);
    const uint32_t ksm = (uint32_t)__cvta_generic_to_shared(Ksm);
    const uint32_t vsm = (uint32_t)__cvta_generic_to_shared(Vsm);
    const uint32_t TSZ = 64 * 72 * 2;

    const int hb = blockIdx.y;
    const int h  = hb >> 2, b = hb & 3;
    const int q0 = blockIdx.x * 128;
    const int t = threadIdx.x, warp = t >> 5, lane = t & 31;
    const int gid = lane >> 2, tig = lane & 3;
    const int lr = lane & 15;
    const int lc = (lane >> 4) * 8;

    const __half* qbase = g_qh + ((size_t)hb * SQ + q0) * DK;
    const __half* kbase = g_kh + (size_t)hb * SQ * DK;
    const __half* vbase = g_vh + (size_t)hb * SQ * DK;

    // ldmatrix offsets
    const uint32_t qoff = ((warp * 16 + lr) * 72 + lc) * 2;
    uint32_t koff[4], voff[4];
#pragma unroll
    for (int p = 0; p < 4; p++) {
        koff[p] = ((p * 16 + ((lane >> 4) & 1) * 8 + (lane & 7)) * 72
                   + ((lane >> 3) & 1) * 8) * 2;
        voff[p] = (lr * 72 + p * 16 + lc) * 2;
    }

    // prologue: Q (4 cp/thread) + K0/V0 (2+2 cp/thread)
#pragma unroll
    for (int u = 0; u < 4; u++) {
        int c = t + u * 256;
        int row = c >> 3, seg = c & 7;
        cp16(qsm + (row * 72 + seg * 8) * 2, qbase + (size_t)row * DK + seg * 8);
    }
#pragma unroll
    for (int u = 0; u < 2; u++) {
        int c = t + u * 256;
        int row = c >> 3, seg = c & 7;
        cp16(ksm + (row * 72 + seg * 8) * 2, kbase + (size_t)row * DK + seg * 8);
        cp16(vsm + (row * 72 + seg * 8) * 2, vbase + (size_t)row * DK + seg * 8);
    }
    cp_commit();
    cp_wait0();
    __syncthreads();

    // Q fragments -> registers (persist for whole kernel)
    uint32_t qf[4][4];
#pragma unroll
    for (int j = 0; j < 4; j++) ldsm4(qf[j], qsm + qoff + j * 16 * 2);

    float Oacc[8][4] = {};
    float rs0 = 0.f, rs1 = 0.f;
    const float NEGINF = __int_as_float(0xff800000u);

    const int rl0 = warp * 16 + gid;         // local q rows owned by this thread
    const int rl1 = rl0 + 8;
    const int* mrow0 = mask + ((size_t)b * SQ + q0 + rl0) * SQ;
    const int* mrow1 = mask + ((size_t)b * SQ + q0 + rl1) * SQ;
    float* srow0 = sc + ((size_t)hb * SQ + q0 + rl0) * SQ;
    float* srow1 = sc + ((size_t)hb * SQ + q0 + rl1) * SQ;

    for (int kb = 0; kb < 16; kb++) {
        const int slot = kb & 1;
        if (kb > 0) { cp_wait0(); __syncthreads(); }
        if (kb + 1 < 16) {
            const int so = slot ^ 1;
            const __half* kp = kbase + (size_t)(kb + 1) * 64 * DK;
            const __half* vp = vbase + (size_t)(kb + 1) * 64 * DK;
#pragma unroll
            for (int u = 0; u < 2; u++) {
                int c = t + u * 256;
                int row = c >> 3, seg = c & 7;
                cp16(ksm + so * TSZ + (row * 72 + seg * 8) * 2, kp + (size_t)row * DK + seg * 8);
                cp16(vsm + so * TSZ + (row * 72 + seg * 8) * 2, vp + (size_t)row * DK + seg * 8);
            }
        }
        cp_commit();

        const uint32_t Kp = ksm + slot * TSZ;
        const uint32_t Vp = vsm + slot * TSZ;

        // S = Q @ K^T : 16q x 64key per warp
        float Sacc[8][4] = {};
#pragma unroll
        for (int j = 0; j < 4; j++) {
            uint32_t bk[8][2];
#pragma unroll
            for (int p = 0; p < 4; p++) {
                uint32_t r[4];
                ldsm4(r, Kp + koff[p] + j * 16 * 2);
                bk[p * 2][0] = r[0]; bk[p * 2][1] = r[1];
                bk[p * 2 + 1][0] = r[2]; bk[p * 2 + 1][1] = r[3];
            }
#pragma unroll
            for (int nt = 0; nt < 8; nt++) mma16(Sacc[nt], qf[j], bk[nt]);
        }

        // scale, mask, write scores (fp32), exp -> register A-fragments
        uint32_t apv[4][4];
        const int cb = kb * 64;
#pragma unroll
        for (int nt = 0; nt < 8; nt++) {
            int cl = cb + nt * 8 + 2 * tig;
            int2 m0 = *(const int2*)(mrow0 + cl);
            int2 m1 = *(const int2*)(mrow1 + cl);
            float s00 = m0.x ? Sacc[nt][0] * 0.125f : NEGINF;
            float s01 = m0.y ? Sacc[nt][1] * 0.125f : NEGINF;
            float s10 = m1.x ? Sacc[nt][2] * 0.125f : NEGINF;
            float s11 = m1.y ? Sacc[nt][3] * 0.125f : NEGINF;
            *(float2*)(srow0 + cl) = make_float2(s00, s01);
            *(float2*)(srow1 + cl) = make_float2(s10, s11);
            float e00 = __expf(s00), e01 = __expf(s01);
            float e10 = __expf(s10), e11 = __expf(s11);
            rs0 += e00 + e01;
            rs1 += e10 + e11;
            int j = nt >> 1;
            if ((nt & 1) == 0) {
                apv[j][0] = h2u(__floats2half2_rn(e00, e01));
                apv[j][1] = h2u(__floats2half2_rn(e10, e11));
            } else {
                apv[j][2] = h2u(__floats2half2_rn(e00, e01));
                apv[j][3] = h2u(__floats2half2_rn(e10, e11));
            }
        }

        // O += P @ V : 16q x 64d per warp, k = 64 keys
#pragma unroll
        for (int j = 0; j < 4; j++) {
            uint32_t bv[8][2];
#pragma unroll
            for (int p = 0; p < 4; p++) {
                uint32_t r[4];
                ldsm4t(r, Vp + voff[p] + j * 16 * 72 * 2);
                bv[p * 2][0] = r[0]; bv[p * 2][1] = r[1];
                bv[p * 2 + 1][0] = r[2]; bv[p * 2 + 1][1] = r[3];
            }
#pragma unroll
            for (int nt = 0; nt < 8; nt++) mma16(Oacc[nt], apv[j], bv[nt]);
        }
    }

    // quad-reduce row sums (tig lanes share a row)
    rs0 += __shfl_xor_sync(0xffffffffu, rs0, 1);
    rs0 += __shfl_xor_sync(0xffffffffu, rs0, 2);
    rs1 += __shfl_xor_sync(0xffffffffu, rs1, 1);
    rs1 += __shfl_xor_sync(0xffffffffu, rs1, 2);
    float inv0 = 1.0f / rs0, inv1 = 1.0f / rs1;

    __half* c0 = g_ch + ((size_t)b * SQ + q0 + rl0) * DM + h * DK;
    __half* c1 = g_ch + ((size_t)b * SQ + q0 + rl1) * DM + h * DK;
#pragma unroll
    for (int nt = 0; nt < 8; nt++) {
        int cl = nt * 8 + 2 * tig;
        *(__half2*)(c0 + cl) = __floats2half2_rn(Oacc[nt][0] * inv0, Oacc[nt][1] * inv0);
        *(__half2*)(c1 + cl) = __floats2half2_rn(Oacc[nt][2] * inv1, Oacc[nt][3] * inv1);
    }
}

// ---------------------------------------------------------------------------
// Kernel 3: out = concat @ Wo, fp16 mma + ldmatrix, BK=32, 3-stage. fp32 out.
// (unchanged from R7)
// ---------------------------------------------------------------------------
__global__ __launch_bounds__(256) void outproj_mma(float* __restrict__ out)
{
    const int row0 = blockIdx.x * 128;
    const int col0 = blockIdx.y * 128;

    extern __shared__ __align__(16) __half sh[];
    __half* As = sh;
    __half* Bs = sh + 3 * 128 * 40;
    const uint32_t sA = (uint32_t)__cvta_generic_to_shared(As);
    const uint32_t sB = (uint32_t)__cvta_generic_to_shared(Bs);
    const uint32_t ASZ = 128 * 40 * 2, BSZ = 32 * 136 * 2;

    const int t    = threadIdx.x;
    const int warp = t >> 5, lane = t & 31;
    const int gid  = lane >> 2, tig = lane & 3;
    const int mb   = (warp >> 1) * 32;
    const int nb   = (warp & 1) * 64;
    const int lr   = lane & 15;
    const int lc   = (lane >> 4) * 8;

    uint32_t aoffm[2], boffn[4];
#pragma unroll
    for (int mt = 0; mt < 2; mt++) aoffm[mt] = ((mb + mt * 16 + lr) * 40 + lc) * 2;
#pragma unroll
    for (int p = 0; p < 4; p++) boffn[p] = (lr * 136 + nb + p * 16 + lc) * 2;

    const __half* aptr[2]; uint32_t aoff[2];
    const __half* bptr[2]; uint32_t boff[2];
#pragma unroll
    for (int u = 0; u < 2; u++) {
        int c = t + u * 256;
        int arow = c >> 2, aseg = c & 3;
        aptr[u] = g_ch + (size_t)(row0 + arow) * DM + aseg * 8;
        aoff[u] = (arow * 40 + aseg * 8) * 2;
        int brow = c >> 4, bseg = c & 15;
        bptr[u] = g_wo + (size_t)brow * DM + col0 + bseg * 8;
        boff[u] = (brow * 136 + bseg * 8) * 2;
    }

    float acc[2][8][4] = {};
    const int NT = 32;

#pragma unroll
    for (int p = 0; p < 2; p++) {
#pragma unroll
        for (int u = 0; u < 2; u++) {
            cp16(sA + p * ASZ + aoff[u], aptr[u] + p * 32);
            cp16(sB + p * BSZ + boff[u], bptr[u] + (size_t)(p * 32) * DM);
        }
        cp_commit();
    }

    int slot = 0;
    for (int tt = 0; tt < NT; tt++) {
        cp_wait1();
        __syncthreads();
        if (tt + 2 < NT) {
            const int ps = (tt + 2) % 3;
            const int kt = (tt + 2) * 32;
#pragma unroll
            for (int u = 0; u < 2; u++) {
                cp16(sA + ps * ASZ + aoff[u], aptr[u] + kt);
                cp16(sB + ps * BSZ + boff[u], bptr[u] + (size_t)kt * DM);
            }
        }
        cp_commit();

        const uint32_t sAs = sA + slot * ASZ;
        const uint32_t sBs = sB + slot * BSZ;
#pragma unroll
        for (int ks = 0; ks < 32; ks += 16) {
            uint32_t a[2][4], b[8][2];
#pragma unroll
            for (int mt = 0; mt < 2; mt++) ldsm4(a[mt], sAs + aoffm[mt] + ks * 2);
#pragma unroll
            for (int p = 0; p < 4; p++) {
                uint32_t r[4];
                ldsm4t(r, sBs + boffn[p] + ks * 136 * 2);
                b[p * 2][0] = r[0]; b[p * 2][1] = r[1];
                b[p * 2 + 1][0] = r[2]; b[p * 2 + 1][1] = r[3];
            }
#pragma unroll
            for (int mt = 0; mt < 2; mt++)
#pragma unroll
                for (int nt = 0; nt < 8; nt++) mma16(acc[mt][nt], a[mt], b[nt]);
        }
        slot = (slot + 1 == 3) ? 0 : slot + 1;
    }

#pragma unroll
    for (int mt = 0; mt < 2; mt++) {
        int r = row0 + mb + mt * 16 + gid;
#pragma unroll
        for (int nt = 0; nt < 8; nt++) {
            int col = col0 + nb + nt * 8 + 2 * tig;
            *(float2*)(out + (size_t)r * DM + col)       = make_float2(acc[mt][nt][0], acc[mt][nt][1]);
            *(float2*)(out + (size_t)(r + 8) * DM + col) = make_float2(acc[mt][nt][2], acc[mt][nt][3]);
        }
    }
}

// ---------------------------------------------------------------------------
extern "C" void kernel_launch(void* const* d_in, const int* in_sizes, int n_in,
                              void* d_out, int out_size)
{
    const float* q    = (const float*)d_in[0];
    const float* k    = (const float*)d_in[1];
    const float* v    = (const float*)d_in[2];
    const int*   mask = (const int*)  d_in[3];
    const float* Wq   = (const float*)d_in[4];
    const float* Wk   = (const float*)d_in[5];
    const float* Wv   = (const float*)d_in[6];
    const float* Wo   = (const float*)d_in[7];

    float* out = (float*)d_out;
    float* scp = out + (size_t)MR * DM;

    static int smem_set = 0;
    if (!smem_set) {
        cudaFuncSetAttribute(proj_mma,    cudaFuncAttributeMaxDynamicSharedMemorySize, 56832);
        cudaFuncSetAttribute(outproj_mma, cudaFuncAttributeMaxDynamicSharedMemorySize, 56832);
        cudaFuncSetAttribute(attn_mma,    cudaFuncAttributeMaxDynamicSharedMemorySize, 55296);
        smem_set = 1;
    }

    prep_all   <<<8192, 256>>>(q, k, v, Wq, Wk, Wv, Wo);
    proj_mma   <<<dim3(32, 8, 3), 256, 56832>>>();
    attn_mma   <<<dim3(8, 64), 256, 55296>>>(mask, scp);
    outproj_mma<<<dim3(32, 8), 256, 56832>>>(out);
}

// round 10
// speedup vs baseline: 5.1055x; 1.0277x over previous
#include <cuda_runtime.h>
#include <cuda_fp16.h>
#include <cstdint>

#define NH 16
#define NB 4
#define SQ 1024
#define DM 1024
#define DK 64
#define MR (NB * SQ)
#define HB (NH * NB)

// fp16 scratch (__device__ globals per allocation-free rule)
__device__ __half g_xq[(size_t)MR * DM];
__device__ __half g_xk[(size_t)MR * DM];
__device__ __half g_xv[(size_t)MR * DM];
__device__ __half g_wq[(size_t)NH * DM * DK];
__device__ __half g_wk[(size_t)NH * DM * DK];
__device__ __half g_wv[(size_t)NH * DM * DK];
__device__ __half g_wo[(size_t)DM * DM];
__device__ __half g_qh[(size_t)HB * SQ * DK];
__device__ __half g_kh[(size_t)HB * SQ * DK];
__device__ __half g_vh[(size_t)HB * SQ * DK];
__device__ __half g_ch[(size_t)MR * DM];

__device__ __forceinline__ uint32_t h2u(__half2 h) { return *(uint32_t*)&h; }

__device__ __forceinline__ void ldsm4(uint32_t* r, uint32_t addr) {
    asm volatile("ldmatrix.sync.aligned.m8n8.x4.shared.b16 {%0,%1,%2,%3}, [%4];"
        : "=r"(r[0]), "=r"(r[1]), "=r"(r[2]), "=r"(r[3]) : "r"(addr));
}
__device__ __forceinline__ void ldsm4t(uint32_t* r, uint32_t addr) {
    asm volatile("ldmatrix.sync.aligned.m8n8.x4.trans.shared.b16 {%0,%1,%2,%3}, [%4];"
        : "=r"(r[0]), "=r"(r[1]), "=r"(r[2]), "=r"(r[3]) : "r"(addr));
}
__device__ __forceinline__ void mma16(float* d, const uint32_t* a, const uint32_t* b) {
    asm volatile("mma.sync.aligned.m16n8k16.row.col.f32.f16.f16.f32 "
        "{%0,%1,%2,%3}, {%4,%5,%6,%7}, {%8,%9}, {%0,%1,%2,%3};"
        : "+f"(d[0]), "+f"(d[1]), "+f"(d[2]), "+f"(d[3])
        : "r"(a[0]), "r"(a[1]), "r"(a[2]), "r"(a[3]), "r"(b[0]), "r"(b[1]));
}
__device__ __forceinline__ void cp16(uint32_t dst, const void* src) {
    asm volatile("cp.async.cg.shared.global [%0], [%1], 16;" :: "r"(dst), "l"(src));
}
__device__ __forceinline__ void cp_commit() { asm volatile("cp.async.commit_group;"); }
__device__ __forceinline__ void cp_wait0() { asm volatile("cp.async.wait_group 0;"); }
__device__ __forceinline__ void cp_wait1() { asm volatile("cp.async.wait_group 1;"); }

// ---------------------------------------------------------------------------
// Kernel 0: single fused fp32->fp16 conversion for all 7 input tensors.
// ---------------------------------------------------------------------------
__global__ __launch_bounds__(256) void prep_all(
    const float* __restrict__ q, const float* __restrict__ k, const float* __restrict__ v,
    const float* __restrict__ wq, const float* __restrict__ wk, const float* __restrict__ wv,
    const float* __restrict__ wo)
{
    const int bb = blockIdx.x;
    const float* src; __half* dst; int inner;
    if (bb < 6144) {
        int which = bb >> 11;
        src = (which == 0) ? q : (which == 1) ? k : v;
        dst = (which == 0) ? g_xq : (which == 1) ? g_xk : g_xv;
        inner = bb & 2047;
    } else {
        int which = (bb - 6144) >> 9;
        src = (which == 0) ? wq : (which == 1) ? wk : (which == 2) ? wv : wo;
        dst = (which == 0) ? g_wq : (which == 1) ? g_wk : (which == 2) ? g_wv : g_wo;
        inner = (bb - 6144) & 511;
    }
    size_t i = (size_t)inner * 256 + threadIdx.x;
    float4 a = ((const float4*)src)[i * 2];
    float4 b = ((const float4*)src)[i * 2 + 1];
    uint4 o;
    o.x = h2u(__floats2half2_rn(a.x, a.y));
    o.y = h2u(__floats2half2_rn(a.z, a.w));
    o.z = h2u(__floats2half2_rn(b.x, b.y));
    o.w = h2u(__floats2half2_rn(b.z, b.w));
    ((uint4*)dst)[i] = o;
}

// ---------------------------------------------------------------------------
// Kernel 1: per-head projections. fp16 mma, BK=64, 3-stage cp.async ring,
// depth-2 register fragment pipeline. A smem [128 m][72 k], B smem [64 k][136 n].
// ---------------------------------------------------------------------------
__global__ __launch_bounds__(256, 2) void proj_mma()
{
    const int which = blockIdx.z;
    const __half* X = (which == 0) ? g_xq : (which == 1) ? g_xk : g_xv;
    const __half* W = (which == 0) ? g_wq : (which == 1) ? g_wk : g_wv;
    __half* O       = (which == 0) ? g_qh : (which == 1) ? g_kh : g_vh;
    const int row0 = blockIdx.x * 128;
    const int col0 = blockIdx.y * 128;

    extern __shared__ __align__(16) __half sh[];
    __half* As = sh;                  // [3][128*72]
    __half* Bs = sh + 3 * 128 * 72;   // [3][64*136]
    const uint32_t sA = (uint32_t)__cvta_generic_to_shared(As);
    const uint32_t sB = (uint32_t)__cvta_generic_to_shared(Bs);
    const uint32_t ASZ = 128 * 72 * 2, BSZ = 64 * 136 * 2;

    const int t    = threadIdx.x;
    const int warp = t >> 5, lane = t & 31;
    const int gid  = lane >> 2, tig = lane & 3;
    const int mb   = (warp >> 1) * 32;
    const int nb   = (warp & 1) * 64;
    const int lr   = lane & 15;
    const int lc   = (lane >> 4) * 8;

    uint32_t aoffm[2], boffn[4];
#pragma unroll
    for (int mt = 0; mt < 2; mt++) aoffm[mt] = ((mb + mt * 16 + lr) * 72 + lc) * 2;
#pragma unroll
    for (int p = 0; p < 4; p++) boffn[p] = (lr * 136 + nb + p * 16 + lc) * 2;

    // cp.async: A 4/thread (128 rows x 8 segs), B 4/thread (64 rows x 16 segs)
    const __half* aptr[4]; uint32_t aoff[4];
    const __half* bptr[4]; uint32_t boff[4];
#pragma unroll
    for (int u = 0; u < 4; u++) {
        int c = t + u * 256;
        int arow = c >> 3, aseg = c & 7;
        aptr[u] = X + (size_t)(row0 + arow) * DM + aseg * 8;
        aoff[u] = (arow * 72 + aseg * 8) * 2;
        int brow = c >> 4, bseg = c & 15;
        int colh = col0 + bseg * 8, hh = colh >> 6, kk = colh & 63;
        bptr[u] = W + (size_t)hh * DM * DK + (size_t)brow * DK + kk;
        boff[u] = (brow * 136 + bseg * 8) * 2;
    }

    float acc[2][8][4] = {};
    const int NT = 16;   // 1024 / 64

#pragma unroll
    for (int p = 0; p < 2; p++) {
#pragma unroll
        for (int u = 0; u < 4; u++) {
            cp16(sA + p * ASZ + aoff[u], aptr[u] + p * 64);
            cp16(sB + p * BSZ + boff[u], bptr[u] + (size_t)(p * 64) * DK);
        }
        cp_commit();
    }

    int slot = 0;
    for (int tt = 0; tt < NT; tt++) {
        cp_wait1();
        __syncthreads();
        if (tt + 2 < NT) {
            const int ps = (tt + 2) % 3;
            const int kt = (tt + 2) * 64;
#pragma unroll
            for (int u = 0; u < 4; u++) {
                cp16(sA + ps * ASZ + aoff[u], aptr[u] + kt);
                cp16(sB + ps * BSZ + boff[u], bptr[u] + (size_t)kt * DK);
            }
        }
        cp_commit();

        const uint32_t sAs = sA + slot * ASZ;
        const uint32_t sBs = sB + slot * BSZ;

        // depth-2 pipelined fragments over 4 k16 steps
        uint32_t a[2][2][4], b[2][8][2];
#pragma unroll
        for (int mt = 0; mt < 2; mt++) ldsm4(a[0][mt], sAs + aoffm[mt]);
#pragma unroll
        for (int p = 0; p < 4; p++) {
            uint32_t r[4];
            ldsm4t(r, sBs + boffn[p]);
            b[0][p * 2][0] = r[0]; b[0][p * 2][1] = r[1];
            b[0][p * 2 + 1][0] = r[2]; b[0][p * 2 + 1][1] = r[3];
        }
#pragma unroll
        for (int ks = 0; ks < 4; ks++) {
            const int cur = ks & 1, nxt = cur ^ 1;
            if (ks < 3) {
                const int ko = (ks + 1) * 16;
#pragma unroll
                for (int mt = 0; mt < 2; mt++) ldsm4(a[nxt][mt], sAs + aoffm[mt] + ko * 2);
#pragma unroll
                for (int p = 0; p < 4; p++) {
                    uint32_t r[4];
                    ldsm4t(r, sBs + boffn[p] + ko * 136 * 2);
                    b[nxt][p * 2][0] = r[0]; b[nxt][p * 2][1] = r[1];
                    b[nxt][p * 2 + 1][0] = r[2]; b[nxt][p * 2 + 1][1] = r[3];
                }
            }
#pragma unroll
            for (int mt = 0; mt < 2; mt++)
#pragma unroll
                for (int nt = 0; nt < 8; nt++) mma16(acc[mt][nt], a[cur][mt], b[cur][nt]);
        }
        slot = (slot + 1 == 3) ? 0 : slot + 1;
    }

#pragma unroll
    for (int mt = 0; mt < 2; mt++) {
        int r0 = row0 + mb + mt * 16 + gid;
        int bb = r0 >> 10, s0 = r0 & 1023;
#pragma unroll
        for (int nt = 0; nt < 8; nt++) {
            int col = col0 + nb + nt * 8 + 2 * tig;
            int hh = col >> 6, kk = col & 63;
            __half* base = O + (size_t)(hh * NB + bb) * SQ * DK;
            *(__half2*)(base + (size_t)s0 * DK + kk) =
                __floats2half2_rn(acc[mt][nt][0], acc[mt][nt][1]);
            *(__half2*)(base + (size_t)(s0 + 8) * DK + kk) =
                __floats2half2_rn(acc[mt][nt][2], acc[mt][nt][3]);
        }
    }
}

// ---------------------------------------------------------------------------
// Kernel 2: fused attention, register-resident P + depth-2 K/V frag pipeline.
// Scores stored with streaming hint (never re-read; keeps mask L2-resident).
// ---------------------------------------------------------------------------
__global__ __launch_bounds__(256, 2) void attn_mma(
    const int* __restrict__ mask, float* __restrict__ sc)
{
    extern __shared__ __align__(16) __half smh[];
    __half* Qs  = smh;                    // [128][72]
    __half* Ksm = Qs + 128 * 72;          // [2][64][72]
    __half* Vsm = Ksm + 2 * 64 * 72;      // [2][64][72]

    const uint32_t qsm = (uint32_t)__cvta_generic_to_shared(Qs);
    const uint32_t ksm = (uint32_t)__cvta_generic_to_shared(Ksm);
    const uint32_t vsm = (uint32_t)__cvta_generic_to_shared(Vsm);
    const uint32_t TSZ = 64 * 72 * 2;

    const int hb = blockIdx.y;
    const int h  = hb >> 2, b = hb & 3;
    const int q0 = blockIdx.x * 128;
    const int t = threadIdx.x, warp = t >> 5, lane = t & 31;
    const int gid = lane >> 2, tig = lane & 3;
    const int lr = lane & 15;
    const int lc = (lane >> 4) * 8;

    const __half* qbase = g_qh + ((size_t)hb * SQ + q0) * DK;
    const __half* kbase = g_kh + (size_t)hb * SQ * DK;
    const __half* vbase = g_vh + (size_t)hb * SQ * DK;

    const uint32_t qoff = ((warp * 16 + lr) * 72 + lc) * 2;
    uint32_t koff[4], voff[4];
#pragma unroll
    for (int p = 0; p < 4; p++) {
        koff[p] = ((p * 16 + ((lane >> 4) & 1) * 8 + (lane & 7)) * 72
                   + ((lane >> 3) & 1) * 8) * 2;
        voff[p] = (lr * 72 + p * 16 + lc) * 2;
    }

#pragma unroll
    for (int u = 0; u < 4; u++) {
        int c = t + u * 256;
        int row = c >> 3, seg = c & 7;
        cp16(qsm + (row * 72 + seg * 8) * 2, qbase + (size_t)row * DK + seg * 8);
    }
#pragma unroll
    for (int u = 0; u < 2; u++) {
        int c = t + u * 256;
        int row = c >> 3, seg = c & 7;
        cp16(ksm + (row * 72 + seg * 8) * 2, kbase + (size_t)row * DK + seg * 8);
        cp16(vsm + (row * 72 + seg * 8) * 2, vbase + (size_t)row * DK + seg * 8);
    }
    cp_commit();
    cp_wait0();
    __syncthreads();

    uint32_t qf[4][4];
#pragma unroll
    for (int j = 0; j < 4; j++) ldsm4(qf[j], qsm + qoff + j * 16 * 2);

    float Oacc[8][4] = {};
    float rs0 = 0.f, rs1 = 0.f;
    const float NEGINF = __int_as_float(0xff800000u);

    const int rl0 = warp * 16 + gid;
    const int rl1 = rl0 + 8;
    const int* mrow0 = mask + ((size_t)b * SQ + q0 + rl0) * SQ;
    const int* mrow1 = mask + ((size_t)b * SQ + q0 + rl1) * SQ;
    float* srow0 = sc + ((size_t)hb * SQ + q0 + rl0) * SQ;
    float* srow1 = sc + ((size_t)hb * SQ + q0 + rl1) * SQ;

    for (int kb = 0; kb < 16; kb++) {
        const int slot = kb & 1;
        if (kb > 0) { cp_wait0(); __syncthreads(); }
        if (kb + 1 < 16) {
            const int so = slot ^ 1;
            const __half* kp = kbase + (size_t)(kb + 1) * 64 * DK;
            const __half* vp = vbase + (size_t)(kb + 1) * 64 * DK;
#pragma unroll
            for (int u = 0; u < 2; u++) {
                int c = t + u * 256;
                int row = c >> 3, seg = c & 7;
                cp16(ksm + so * TSZ + (row * 72 + seg * 8) * 2, kp + (size_t)row * DK + seg * 8);
                cp16(vsm + so * TSZ + (row * 72 + seg * 8) * 2, vp + (size_t)row * DK + seg * 8);
            }
        }
        cp_commit();

        const uint32_t Kp = ksm + slot * TSZ;
        const uint32_t Vp = vsm + slot * TSZ;

        // S = Q @ K^T : depth-2 pipelined over j
        float Sacc[8][4] = {};
        {
            uint32_t bk[2][8][2];
#pragma unroll
            for (int p = 0; p < 4; p++) {
                uint32_t r[4];
                ldsm4(r, Kp + koff[p]);
                bk[0][p * 2][0] = r[0]; bk[0][p * 2][1] = r[1];
                bk[0][p * 2 + 1][0] = r[2]; bk[0][p * 2 + 1][1] = r[3];
            }
#pragma unroll
            for (int j = 0; j < 4; j++) {
                const int cur = j & 1, nxt = cur ^ 1;
                if (j < 3) {
#pragma unroll
                    for (int p = 0; p < 4; p++) {
                        uint32_t r[4];
                        ldsm4(r, Kp + koff[p] + (j + 1) * 16 * 2);
                        bk[nxt][p * 2][0] = r[0]; bk[nxt][p * 2][1] = r[1];
                        bk[nxt][p * 2 + 1][0] = r[2]; bk[nxt][p * 2 + 1][1] = r[3];
                    }
                }
#pragma unroll
                for (int nt = 0; nt < 8; nt++) mma16(Sacc[nt], qf[j], bk[cur][nt]);
            }
        }

        // scale, mask, streaming score stores, exp -> register A-fragments
        uint32_t apv[4][4];
        const int cb = kb * 64;
#pragma unroll
        for (int nt = 0; nt < 8; nt++) {
            int cl = cb + nt * 8 + 2 * tig;
            int2 m0 = *(const int2*)(mrow0 + cl);
            int2 m1 = *(const int2*)(mrow1 + cl);
            float s00 = m0.x ? Sacc[nt][0] * 0.125f : NEGINF;
            float s01 = m0.y ? Sacc[nt][1] * 0.125f : NEGINF;
            float s10 = m1.x ? Sacc[nt][2] * 0.125f : NEGINF;
            float s11 = m1.y ? Sacc[nt][3] * 0.125f : NEGINF;
            __stcs((float2*)(srow0 + cl), make_float2(s00, s01));
            __stcs((float2*)(srow1 + cl), make_float2(s10, s11));
            float e00 = __expf(s00), e01 = __expf(s01);
            float e10 = __expf(s10), e11 = __expf(s11);
            rs0 += e00 + e01;
            rs1 += e10 + e11;
            int j = nt >> 1;
            if ((nt & 1) == 0) {
                apv[j][0] = h2u(__floats2half2_rn(e00, e01));
                apv[j][1] = h2u(__floats2half2_rn(e10, e11));
            } else {
                apv[j][2] = h2u(__floats2half2_rn(e00, e01));
                apv[j][3] = h2u(__floats2half2_rn(e10, e11));
            }
        }

        // O += P @ V : depth-2 pipelined over j
        {
            uint32_t bv[2][8][2];
#pragma unroll
            for (int p = 0; p < 4; p++) {
                uint32_t r[4];
                ldsm4t(r, Vp + voff[p]);
                bv[0][p * 2][0] = r[0]; bv[0][p * 2][1] = r[1];
                bv[0][p * 2 + 1][0] = r[2]; bv[0][p * 2 + 1][1] = r[3];
            }
#pragma unroll
            for (int j = 0; j < 4; j++) {
                const int cur = j & 1, nxt = cur ^ 1;
                if (j < 3) {
#pragma unroll
                    for (int p = 0; p < 4; p++) {
                        uint32_t r[4];
                        ldsm4t(r, Vp + voff[p] + (j + 1) * 16 * 72 * 2);
                        bv[nxt][p * 2][0] = r[0]; bv[nxt][p * 2][1] = r[1];
                        bv[nxt][p * 2 + 1][0] = r[2]; bv[nxt][p * 2 + 1][1] = r[3];
                    }
                }
#pragma unroll
                for (int nt = 0; nt < 8; nt++) mma16(Oacc[nt], apv[j], bv[cur][nt]);
            }
        }
    }

    rs0 += __shfl_xor_sync(0xffffffffu, rs0, 1);
    rs0 += __shfl_xor_sync(0xffffffffu, rs0, 2);
    rs1 += __shfl_xor_sync(0xffffffffu, rs1, 1);
    rs1 += __shfl_xor_sync(0xffffffffu, rs1, 2);
    float inv0 = 1.0f / rs0, inv1 = 1.0f / rs1;

    __half* c0 = g_ch + ((size_t)b * SQ + q0 + rl0) * DM + h * DK;
    __half* c1 = g_ch + ((size_t)b * SQ + q0 + rl1) * DM + h * DK;
#pragma unroll
    for (int nt = 0; nt < 8; nt++) {
        int cl = nt * 8 + 2 * tig;
        *(__half2*)(c0 + cl) = __floats2half2_rn(Oacc[nt][0] * inv0, Oacc[nt][1] * inv0);
        *(__half2*)(c1 + cl) = __floats2half2_rn(Oacc[nt][2] * inv1, Oacc[nt][3] * inv1);
    }
}

// ---------------------------------------------------------------------------
// Kernel 3: out = concat @ Wo, BK=64, 3-stage, depth-2 frag pipeline. fp32 out.
// ---------------------------------------------------------------------------
__global__ __launch_bounds__(256, 2) void outproj_mma(float* __restrict__ out)
{
    const int row0 = blockIdx.x * 128;
    const int col0 = blockIdx.y * 128;

    extern __shared__ __align__(16) __half sh[];
    __half* As = sh;
    __half* Bs = sh + 3 * 128 * 72;
    const uint32_t sA = (uint32_t)__cvta_generic_to_shared(As);
    const uint32_t sB = (uint32_t)__cvta_generic_to_shared(Bs);
    const uint32_t ASZ = 128 * 72 * 2, BSZ = 64 * 136 * 2;

    const int t    = threadIdx.x;
    const int warp = t >> 5, lane = t & 31;
    const int gid  = lane >> 2, tig = lane & 3;
    const int mb   = (warp >> 1) * 32;
    const int nb   = (warp & 1) * 64;
    const int lr   = lane & 15;
    const int lc   = (lane >> 4) * 8;

    uint32_t aoffm[2], boffn[4];
#pragma unroll
    for (int mt = 0; mt < 2; mt++) aoffm[mt] = ((mb + mt * 16 + lr) * 72 + lc) * 2;
#pragma unroll
    for (int p = 0; p < 4; p++) boffn[p] = (lr * 136 + nb + p * 16 + lc) * 2;

    const __half* aptr[4]; uint32_t aoff[4];
    const __half* bptr[4]; uint32_t boff[4];
#pragma unroll
    for (int u = 0; u < 4; u++) {
        int c = t + u * 256;
        int arow = c >> 3, aseg = c & 7;
        aptr[u] = g_ch + (size_t)(row0 + arow) * DM + aseg * 8;
        aoff[u] = (arow * 72 + aseg * 8) * 2;
        int brow = c >> 4, bseg = c & 15;
        bptr[u] = g_wo + (size_t)brow * DM + col0 + bseg * 8;
        boff[u] = (brow * 136 + bseg * 8) * 2;
    }

    float acc[2][8][4] = {};
    const int NT = 16;

#pragma unroll
    for (int p = 0; p < 2; p++) {
#pragma unroll
        for (int u = 0; u < 4; u++) {
            cp16(sA + p * ASZ + aoff[u], aptr[u] + p * 64);
            cp16(sB + p * BSZ + boff[u], bptr[u] + (size_t)(p * 64) * DM);
        }
        cp_commit();
    }

    int slot = 0;
    for (int tt = 0; tt < NT; tt++) {
        cp_wait1();
        __syncthreads();
        if (tt + 2 < NT) {
            const int ps = (tt + 2) % 3;
            const int kt = (tt + 2) * 64;
#pragma unroll
            for (int u = 0; u < 4; u++) {
                cp16(sA + ps * ASZ + aoff[u], aptr[u] + kt);
                cp16(sB + ps * BSZ + boff[u], bptr[u] + (size_t)kt * DM);
            }
        }
        cp_commit();

        const uint32_t sAs = sA + slot * ASZ;
        const uint32_t sBs = sB + slot * BSZ;

        uint32_t a[2][2][4], b[2][8][2];
#pragma unroll
        for (int mt = 0; mt < 2; mt++) ldsm4(a[0][mt], sAs + aoffm[mt]);
#pragma unroll
        for (int p = 0; p < 4; p++) {
            uint32_t r[4];
            ldsm4t(r, sBs + boffn[p]);
            b[0][p * 2][0] = r[0]; b[0][p * 2][1] = r[1];
            b[0][p * 2 + 1][0] = r[2]; b[0][p * 2 + 1][1] = r[3];
        }
#pragma unroll
        for (int ks = 0; ks < 4; ks++) {
            const int cur = ks & 1, nxt = cur ^ 1;
            if (ks < 3) {
                const int ko = (ks + 1) * 16;
#pragma unroll
                for (int mt = 0; mt < 2; mt++) ldsm4(a[nxt][mt], sAs + aoffm[mt] + ko * 2);
#pragma unroll
                for (int p = 0; p < 4; p++) {
                    uint32_t r[4];
                    ldsm4t(r, sBs + boffn[p] + ko * 136 * 2);
                    b[nxt][p * 2][0] = r[0]; b[nxt][p * 2][1] = r[1];
                    b[nxt][p * 2 + 1][0] = r[2]; b[nxt][p * 2 + 1][1] = r[3];
                }
            }
#pragma unroll
            for (int mt = 0; mt < 2; mt++)
#pragma unroll
                for (int nt = 0; nt < 8; nt++) mma16(acc[mt][nt], a[cur][mt], b[cur][nt]);
        }
        slot = (slot + 1 == 3) ? 0 : slot + 1;
    }

#pragma unroll
    for (int mt = 0; mt < 2; mt++) {
        int r = row0 + mb + mt * 16 + gid;
#pragma unroll
        for (int nt = 0; nt < 8; nt++) {
            int col = col0 + nb + nt * 8 + 2 * tig;
            *(float2*)(out + (size_t)r * DM + col)       = make_float2(acc[mt][nt][0], acc[mt][nt][1]);
            *(float2*)(out + (size_t)(r + 8) * DM + col) = make_float2(acc[mt][nt][2], acc[mt][nt][3]);
        }
    }
}

// ---------------------------------------------------------------------------
extern "C" void kernel_launch(void* const* d_in, const int* in_sizes, int n_in,
                              void* d_out, int out_size)
{
    const float* q    = (const float*)d_in[0];
    const float* k    = (const float*)d_in[1];
    const float* v    = (const float*)d_in[2];
    const int*   mask = (const int*)  d_in[3];
    const float* Wq   = (const float*)d_in[4];
    const float* Wk   = (const float*)d_in[5];
    const float* Wv   = (const float*)d_in[6];
    const float* Wo   = (const float*)d_in[7];

    float* out = (float*)d_out;
    float* scp = out + (size_t)MR * DM;

    static int smem_set = 0;
    if (!smem_set) {
        cudaFuncSetAttribute(proj_mma,    cudaFuncAttributeMaxDynamicSharedMemorySize, 107520);
        cudaFuncSetAttribute(outproj_mma, cudaFuncAttributeMaxDynamicSharedMemorySize, 107520);
        cudaFuncSetAttribute(attn_mma,    cudaFuncAttributeMaxDynamicSharedMemorySize, 55296);
        smem_set = 1;
    }

    prep_all   <<<8192, 256>>>(q, k, v, Wq, Wk, Wv, Wo);
    proj_mma   <<<dim3(32, 8, 3), 256, 107520>>>();
    attn_mma   <<<dim3(8, 64), 256, 55296>>>(mask, scp);
    outproj_mma<<<dim3(32, 8), 256, 107520>>>(out);
}